// round 5
// baseline (speedup 1.0000x reference)
#include <cuda_runtime.h>
#include <cuda_bf16.h>
#include <cstdint>

#define N_NODES 50000
#define N_EDGES 800000
#define IN_DIM  256
#define H1      512
#define H2      128
#define M_PAD   50048   // multiple of 128

// -------------------- scratch --------------------
__device__ float g_deg [N_NODES];
__device__ float g_dinv[N_NODES];
__device__ float g_agg1[(size_t)M_PAD * IN_DIM];
__device__ float g_feat1[(size_t)M_PAD * H1];
__device__ float g_xw2 [(size_t)M_PAD * H2];

// -------------------- f32x2 helpers --------------------
__device__ __forceinline__ void ffma2(uint64_t& d, uint64_t a, uint64_t b) {
    asm("fma.rn.f32x2 %0, %1, %2, %0;" : "+l"(d) : "l"(a), "l"(b));
}
__device__ __forceinline__ uint64_t dup2(float v) {
    uint64_t r; asm("mov.b64 %0, {%1, %1};" : "=l"(r) : "f"(v)); return r;
}
__device__ __forceinline__ float2 unpack2(uint64_t p) {
    float2 v; asm("mov.b64 {%0, %1}, %2;" : "=f"(v.x), "=f"(v.y) : "l"(p)); return v;
}
__device__ __forceinline__ void red_add_v4(float* addr, float a, float b, float c, float d) {
    asm volatile("red.global.add.v4.f32 [%0], {%1, %2, %3, %4};"
                 :: "l"(addr), "f"(a), "f"(b), "f"(c), "f"(d) : "memory");
}

// -------------------- small elementwise kernels --------------------
__global__ void deg_init(float* deg, int n) {
    int i = blockIdx.x * blockDim.x + threadIdx.x;
    if (i < n) deg[i] = 1.0f;
}
__global__ void deg_accum(const int* __restrict__ col, const float* __restrict__ ew,
                          float* deg, int E) {
    int e = blockIdx.x * blockDim.x + threadIdx.x;
    if (e < E) atomicAdd(&deg[col[e]], ew[e]);
}
__global__ void deg_rsqrt(const float* __restrict__ deg, float* dinv, int n) {
    int i = blockIdx.x * blockDim.x + threadIdx.x;
    if (i < n) {
        float d = deg[i];
        dinv[i] = d > 0.f ? rsqrtf(d) : 0.f;
    }
}
__global__ void selfloop_init(const float4* __restrict__ src, float4* __restrict__ dst,
                              const float* __restrict__ dinv, int n_nodes, int d4) {
    long idx = (long)blockIdx.x * blockDim.x + threadIdx.x;
    long total = (long)n_nodes * d4;
    if (idx >= total) return;
    int node = (int)(idx / d4);
    float s = dinv[node]; s = s * s;
    float4 v = src[idx];
    dst[idx] = make_float4(s * v.x, s * v.y, s * v.z, s * v.w);
}

// -------------------- edge aggregation (warp/edge, red.v4) --------------------
template <int D>
__global__ void agg_edges(const float4* __restrict__ src, float4* __restrict__ dst,
                          const int* __restrict__ row, const int* __restrict__ col,
                          const float* __restrict__ ew, const float* __restrict__ dinv,
                          int E) {
    int e = (int)(((long)blockIdx.x * blockDim.x + threadIdx.x) >> 5);
    if (e >= E) return;
    int lane = threadIdx.x & 31;
    int r = row[e], c = col[e];
    float s = dinv[r] * ew[e] * dinv[c];
    const float4* srow = src + (size_t)r * (D / 4);
    float4* drow = dst + (size_t)c * (D / 4);
#pragma unroll
    for (int i = 0; i < D / 128; i++) {
        int q = lane + i * 32;
        float4 v = srow[q];
        red_add_v4((float*)(drow + q), s * v.x, s * v.y, s * v.z, s * v.w);
    }
}

// -------------------- SGEMM with packed f32x2 FMA --------------------
// Tile: BM x 128, BK=8; per thread TM x 8 outputs (TM x 4 f32x2 pairs).
// A stored duplicated in smem ((a,a) u64) so FFMA2 operands load directly.
// Requires M % BM == 0, N % 128 == 0, K % 8 == 0.
template <int TM>
__global__ __launch_bounds__(256, 2)
void sgemm_f32x2(const float* __restrict__ A, const float* __restrict__ B,
                 float* __restrict__ C, int M, int N, int K,
                 const float* __restrict__ bias, const float* __restrict__ alpha) {
    constexpr int BM = 16 * TM, BN = 128, BK = 8;
    constexpr int A4 = BM * BK / 4;   // float4 loads for A tile

    __shared__ uint64_t As2[2][BK][BM];  // duplicated (a,a) pairs
    __shared__ float    Bs [2][BK][BN];

    const int tid  = threadIdx.x;
    const int crow = tid >> 4;          // 0..15
    const int ccol = tid & 15;          // 0..15

    const float* Ab = A + (size_t)blockIdx.y * BM * K;
    const float* Bb = B + (size_t)blockIdx.x * BN;

    const int arow = tid >> 1;          // A: 2 float4 per row (BK=8)
    const int ak   = (tid & 1) * 4;
    const int brow = tid >> 5;          // B: 8 rows x 32 float4
    const int bcol = (tid & 31) * 4;

    uint64_t acc[TM][4];
#pragma unroll
    for (int i = 0; i < TM; i++)
#pragma unroll
        for (int j = 0; j < 4; j++) acc[i][j] = 0ull;

    // prologue: tile 0
    if (tid < A4) {
        float4 a = *(const float4*)(Ab + (size_t)arow * K + ak);
        As2[0][ak + 0][arow] = dup2(a.x);
        As2[0][ak + 1][arow] = dup2(a.y);
        As2[0][ak + 2][arow] = dup2(a.z);
        As2[0][ak + 3][arow] = dup2(a.w);
    }
    *(float4*)&Bs[0][brow][bcol] = *(const float4*)(Bb + (size_t)brow * N + bcol);
    __syncthreads();

    int buf = 0;
    for (int k0 = 0; k0 < K; k0 += BK) {
        float4 an, bn;
        const bool more = (k0 + BK) < K;
        if (more) {
            if (tid < A4) an = *(const float4*)(Ab + (size_t)arow * K + k0 + BK + ak);
            bn = *(const float4*)(Bb + (size_t)(k0 + BK + brow) * N + bcol);
        }
#pragma unroll
        for (int k = 0; k < BK; k++) {
            uint64_t a2[TM], b2[4];
#pragma unroll
            for (int i = 0; i < TM; i += 2) {
                ulonglong2 p = *(const ulonglong2*)&As2[buf][k][crow * TM + i];
                a2[i] = p.x; a2[i + 1] = p.y;
            }
            {
                ulonglong2 p0 = *(const ulonglong2*)&Bs[buf][k][ccol * 8 + 0];
                ulonglong2 p1 = *(const ulonglong2*)&Bs[buf][k][ccol * 8 + 4];
                b2[0] = p0.x; b2[1] = p0.y; b2[2] = p1.x; b2[3] = p1.y;
            }
#pragma unroll
            for (int i = 0; i < TM; i++)
#pragma unroll
                for (int j = 0; j < 4; j++)
                    ffma2(acc[i][j], a2[i], b2[j]);
        }
        if (more) {
            int nb = buf ^ 1;
            if (tid < A4) {
                As2[nb][ak + 0][arow] = dup2(an.x);
                As2[nb][ak + 1][arow] = dup2(an.y);
                As2[nb][ak + 2][arow] = dup2(an.z);
                As2[nb][ak + 3][arow] = dup2(an.w);
            }
            *(float4*)&Bs[nb][brow][bcol] = bn;
            __syncthreads();
            buf = nb;
        }
    }

    const float al = alpha ? alpha[0] : 0.f;
    float* Cb = C + (size_t)blockIdx.y * BM * N + (size_t)blockIdx.x * BN;
#pragma unroll
    for (int i = 0; i < TM; i++) {
        const int r = crow * TM + i;
#pragma unroll
        for (int jp = 0; jp < 4; jp += 2) {
            float2 u0 = unpack2(acc[i][jp]);
            float2 u1 = unpack2(acc[i][jp + 1]);
            float4 v = make_float4(u0.x, u0.y, u1.x, u1.y);
            const int c = ccol * 8 + jp * 2;
            if (bias) {
                const int gc = blockIdx.x * BN + c;
                v.x += bias[gc + 0]; v.y += bias[gc + 1];
                v.z += bias[gc + 2]; v.w += bias[gc + 3];
                v.x = v.x >= 0.f ? v.x : al * v.x;
                v.y = v.y >= 0.f ? v.y : al * v.y;
                v.z = v.z >= 0.f ? v.z : al * v.z;
                v.w = v.w >= 0.f ? v.w : al * v.w;
            }
            *(float4*)(Cb + (size_t)r * N + c) = v;
        }
    }
}

// out = prelu(out + b2)
__global__ void finalize_kernel(float4* __restrict__ out, const float* __restrict__ b2,
                                const float* __restrict__ alpha, long n4) {
    long i = (long)blockIdx.x * blockDim.x + threadIdx.x;
    if (i >= n4) return;
    float4 v = out[i];
    int d = (int)((i * 4) & (H2 - 1));
    float a = alpha[0];
    v.x += b2[d + 0]; v.y += b2[d + 1]; v.z += b2[d + 2]; v.w += b2[d + 3];
    v.x = v.x >= 0.f ? v.x : a * v.x;
    v.y = v.y >= 0.f ? v.y : a * v.y;
    v.z = v.z >= 0.f ? v.z : a * v.z;
    v.w = v.w >= 0.f ? v.w : a * v.w;
    out[i] = v;
}

// -------------------- launch --------------------
extern "C" void kernel_launch(void* const* d_in, const int* in_sizes, int n_in,
                              void* d_out, int out_size) {
    const float* x     = (const float*)d_in[0];
    const float* ew    = (const float*)d_in[1];
    const float* W1    = (const float*)d_in[2];
    const float* b1    = (const float*)d_in[3];
    const float* W2    = (const float*)d_in[4];
    const float* b2    = (const float*)d_in[5];
    const float* alpha = (const float*)d_in[6];
    const int*   eidx  = (const int*)  d_in[7];

    const int E = in_sizes[1];
    const int N = in_sizes[0] / IN_DIM;
    const int* row = eidx;
    const int* col = eidx + E;

    float* out = (float*)d_out;

    float *deg, *dinv, *agg1, *feat1, *xw2;
    cudaGetSymbolAddress((void**)&deg,   g_deg);
    cudaGetSymbolAddress((void**)&dinv,  g_dinv);
    cudaGetSymbolAddress((void**)&agg1,  g_agg1);
    cudaGetSymbolAddress((void**)&feat1, g_feat1);
    cudaGetSymbolAddress((void**)&xw2,   g_xw2);

    // 1) degrees + dinv
    deg_init<<<(N + 255) / 256, 256>>>(deg, N);
    deg_accum<<<(E + 255) / 256, 256>>>(col, ew, deg, E);
    deg_rsqrt<<<(N + 255) / 256, 256>>>(deg, dinv, N);

    // 2) layer-1 aggregation at D=256: agg1 = A_norm @ x
    {
        long n4 = (long)N * (IN_DIM / 4);
        selfloop_init<<<(int)((n4 + 255) / 256), 256>>>((const float4*)x, (float4*)agg1, dinv, N, IN_DIM / 4);
        long threads = (long)E * 32;
        agg_edges<IN_DIM><<<(int)((threads + 255) / 256), 256>>>(
            (const float4*)x, (float4*)agg1, row, col, ew, dinv, E);
    }

    // 3) GEMM1: feat1 = prelu(agg1 @ W1 + b1)   [50048,256]x[256,512]
    {
        dim3 grid(H1 / 128, M_PAD / 128);
        sgemm_f32x2<8><<<grid, 256>>>(agg1, W1, feat1, M_PAD, H1, IN_DIM, b1, alpha);
    }

    // 4) GEMM2: xw2 = feat1 @ W2   [50048,512]x[512,128], BM=64 for wave balance
    {
        dim3 grid(H2 / 128, M_PAD / 64);
        sgemm_f32x2<4><<<grid, 256>>>(feat1, W2, xw2, M_PAD, H2, H1, nullptr, nullptr);
    }

    // 5) layer-2 aggregation at D=128 into d_out
    {
        long n4 = (long)N * (H2 / 4);
        selfloop_init<<<(int)((n4 + 255) / 256), 256>>>((const float4*)xw2, (float4*)out, dinv, N, H2 / 4);
        long threads = (long)E * 32;
        agg_edges<H2><<<(int)((threads + 255) / 256), 256>>>(
            (const float4*)xw2, (float4*)out, row, col, ew, dinv, E);
    }

    // 6) out = prelu(out + b2)
    {
        long n4 = (long)N * (H2 / 4);
        finalize_kernel<<<(int)((n4 + 255) / 256), 256>>>((float4*)out, b2, alpha, n4);
    }
}

// round 7
// speedup vs baseline: 1.5477x; 1.5477x over previous
#include <cuda_runtime.h>
#include <cuda_bf16.h>
#include <cstdint>

#define N_NODES 50000
#define N_EDGES 800000
#define IN_DIM  256
#define H1      512
#define H2      128
#define M_PAD   50048   // multiple of 128

// -------------------- scratch --------------------
__device__ float g_deg [N_NODES];
__device__ float g_dinv[N_NODES];
__device__ float g_agg1[(size_t)M_PAD * IN_DIM];           // A_norm @ x (fp32)
__device__ float g_xw2 [(size_t)M_PAD * H2];               // feat1 @ W2 (fp32)
__device__ __nv_bfloat16 g_a1hi[(size_t)M_PAD * IN_DIM];   // agg1 split
__device__ __nv_bfloat16 g_a1lo[(size_t)M_PAD * IN_DIM];
__device__ __nv_bfloat16 g_f1hi[(size_t)M_PAD * H1];       // feat1 split
__device__ __nv_bfloat16 g_f1lo[(size_t)M_PAD * H1];
__device__ __nv_bfloat16 g_w1thi[(size_t)H1 * IN_DIM];     // W1^T split [512,256]
__device__ __nv_bfloat16 g_w1tlo[(size_t)H1 * IN_DIM];
__device__ __nv_bfloat16 g_w2thi[(size_t)H2 * H1];         // W2^T split [128,512]
__device__ __nv_bfloat16 g_w2tlo[(size_t)H2 * H1];

// -------------------- helpers --------------------
__device__ __forceinline__ void red_add_v4(float* addr, float a, float b, float c, float d) {
    asm volatile("red.global.add.v4.f32 [%0], {%1, %2, %3, %4};"
                 :: "l"(addr), "f"(a), "f"(b), "f"(c), "f"(d) : "memory");
}

__device__ __forceinline__ void mma_bf16(float* c, const uint32_t* a, const uint32_t* b) {
    asm volatile(
        "mma.sync.aligned.m16n8k16.row.col.f32.bf16.bf16.f32 "
        "{%0,%1,%2,%3}, {%4,%5,%6,%7}, {%8,%9}, {%0,%1,%2,%3};"
        : "+f"(c[0]), "+f"(c[1]), "+f"(c[2]), "+f"(c[3])
        : "r"(a[0]), "r"(a[1]), "r"(a[2]), "r"(a[3]), "r"(b[0]), "r"(b[1]));
}

// -------------------- small elementwise kernels --------------------
__global__ void deg_init(float* deg, int n) {
    int i = blockIdx.x * blockDim.x + threadIdx.x;
    if (i < n) deg[i] = 1.0f;
}
__global__ void deg_accum(const int* __restrict__ col, const float* __restrict__ ew,
                          float* deg, int E) {
    int e = blockIdx.x * blockDim.x + threadIdx.x;
    if (e < E) atomicAdd(&deg[col[e]], ew[e]);
}
__global__ void deg_rsqrt(const float* __restrict__ deg, float* dinv, int n) {
    int i = blockIdx.x * blockDim.x + threadIdx.x;
    if (i < n) { float d = deg[i]; dinv[i] = d > 0.f ? rsqrtf(d) : 0.f; }
}
__global__ void selfloop_init(const float4* __restrict__ src, float4* __restrict__ dst,
                              const float* __restrict__ dinv, int n_nodes, int d4) {
    long idx = (long)blockIdx.x * blockDim.x + threadIdx.x;
    long total = (long)n_nodes * d4;
    if (idx >= total) return;
    int node = (int)(idx / d4);
    float s = dinv[node]; s = s * s;
    float4 v = src[idx];
    dst[idx] = make_float4(s * v.x, s * v.y, s * v.z, s * v.w);
}

// split fp32 -> bf16 hi + bf16 lo (vectorized by 4)
__global__ void decomp4(const float4* __restrict__ src, uint2* __restrict__ hi,
                        uint2* __restrict__ lo, long n4) {
    long i = (long)blockIdx.x * blockDim.x + threadIdx.x;
    if (i >= n4) return;
    float4 v = src[i];
    __nv_bfloat16 h0 = __float2bfloat16(v.x), h1 = __float2bfloat16(v.y);
    __nv_bfloat16 h2 = __float2bfloat16(v.z), h3 = __float2bfloat16(v.w);
    __nv_bfloat16 l0 = __float2bfloat16(v.x - __bfloat162float(h0));
    __nv_bfloat16 l1 = __float2bfloat16(v.y - __bfloat162float(h1));
    __nv_bfloat16 l2 = __float2bfloat16(v.z - __bfloat162float(h2));
    __nv_bfloat16 l3 = __float2bfloat16(v.w - __bfloat162float(h3));
    __nv_bfloat162 hp0; hp0.x = h0; hp0.y = h1;
    __nv_bfloat162 hp1; hp1.x = h2; hp1.y = h3;
    __nv_bfloat162 lp0; lp0.x = l0; lp0.y = l1;
    __nv_bfloat162 lp1; lp1.x = l2; lp1.y = l3;
    hi[i] = make_uint2(*(uint32_t*)&hp0, *(uint32_t*)&hp1);
    lo[i] = make_uint2(*(uint32_t*)&lp0, *(uint32_t*)&lp1);
}

// transpose + split: src[K,N] fp32 -> hi/lo[N,K] bf16
__global__ void decompT(const float* __restrict__ src, __nv_bfloat16* __restrict__ hi,
                        __nv_bfloat16* __restrict__ lo, int K, int N) {
    int i = blockIdx.x * blockDim.x + threadIdx.x;
    if (i >= K * N) return;
    int k = i / N, n = i % N;
    float v = src[i];
    __nv_bfloat16 h = __float2bfloat16(v);
    hi[(size_t)n * K + k] = h;
    lo[(size_t)n * K + k] = __float2bfloat16(v - __bfloat162float(h));
}

// -------------------- edge aggregation (warp/edge, red.v4) --------------------
template <int D>
__global__ void agg_edges(const float4* __restrict__ src, float4* __restrict__ dst,
                          const int* __restrict__ row, const int* __restrict__ col,
                          const float* __restrict__ ew, const float* __restrict__ dinv,
                          int E) {
    int e = (int)(((long)blockIdx.x * blockDim.x + threadIdx.x) >> 5);
    if (e >= E) return;
    int lane = threadIdx.x & 31;
    int r = row[e], c = col[e];
    float s = dinv[r] * ew[e] * dinv[c];
    const float4* srow = src + (size_t)r * (D / 4);
    float4* drow = dst + (size_t)c * (D / 4);
#pragma unroll
    for (int i = 0; i < D / 128; i++) {
        int q = lane + i * 32;
        float4 v = srow[q];
        red_add_v4((float*)(drow + q), s * v.x, s * v.y, s * v.z, s * v.w);
    }
}

// -------------------- bf16x3 GEMM via warp mma.sync (HMMA) --------------------
// C[M,Nc] = (Ahi+Alo)[M,K] @ (Bhi+Blo)^T, B stored [Nc,K] row-major.
// Block 128x128, 8 warps as 2(m) x 4(n), warp tile 64x32, BK=32 smem chunks.
// OUT_MODE 0: fp32 C0. OUT_MODE 1: bias+PReLU, emit bf16 hi(C0)/lo(C1).
#define SPAD 40   // smem row stride in bf16 (32 data + 8 pad)

template <int OUT_MODE>
__global__ __launch_bounds__(256)
void gemm_mma(const __nv_bfloat16* __restrict__ Ahi, const __nv_bfloat16* __restrict__ Alo,
              const __nv_bfloat16* __restrict__ Bhi, const __nv_bfloat16* __restrict__ Blo,
              void* C0, void* C1, int Nc, int K,
              const float* __restrict__ bias, const float* __restrict__ alpha) {
    __shared__ __nv_bfloat16 Ash[128 * SPAD];
    __shared__ __nv_bfloat16 Asl[128 * SPAD];
    __shared__ __nv_bfloat16 Bsh[128 * SPAD];
    __shared__ __nv_bfloat16 Bsl[128 * SPAD];

    const int tid  = threadIdx.x;
    const int wid  = tid >> 5;
    const int lane = tid & 31;
    const int wm   = wid >> 2;          // 0..1
    const int wn   = wid & 3;           // 0..3
    const int m0   = blockIdx.y * 128;
    const int n0   = blockIdx.x * 128;
    const int r4   = lane >> 2;         // 0..7
    const int t2   = (lane & 3) * 2;    // 0,2,4,6

    float acc[4][4][4];
#pragma unroll
    for (int i = 0; i < 4; i++)
#pragma unroll
        for (int j = 0; j < 4; j++)
#pragma unroll
            for (int q = 0; q < 4; q++) acc[i][j][q] = 0.f;

    const int ldr = tid >> 2;           // gmem->smem: row this thread loads (pair of uint4)
    const int ldq = tid & 3;            // which 8-bf16 group

    for (int kc = 0; kc < K; kc += 32) {
        __syncthreads();   // protect smem from previous iteration's readers
        // load 4 tiles: [128 rows][32 bf16] each; 2 uint4 per thread per tile
        {
            const __nv_bfloat16* gA_h = Ahi + (size_t)(m0 + ldr) * K + kc + ldq * 8;
            const __nv_bfloat16* gA_l = Alo + (size_t)(m0 + ldr) * K + kc + ldq * 8;
            const __nv_bfloat16* gB_h = Bhi + (size_t)(n0 + ldr) * K + kc + ldq * 8;
            const __nv_bfloat16* gB_l = Blo + (size_t)(n0 + ldr) * K + kc + ldq * 8;
#pragma unroll
            for (int h = 0; h < 2; h++) {   // rows ldr and ldr+64
                const size_t go = (size_t)h * 64 * K;
                const int so = (ldr + h * 64) * SPAD + ldq * 8;
                *(uint4*)(Ash + so) = *(const uint4*)(gA_h + go);
                *(uint4*)(Asl + so) = *(const uint4*)(gA_l + go);
                *(uint4*)(Bsh + so) = *(const uint4*)(gB_h + go);
                *(uint4*)(Bsl + so) = *(const uint4*)(gB_l + go);
            }
        }
        __syncthreads();

#pragma unroll
        for (int kk = 0; kk < 32; kk += 16) {
            // B fragments for this warp's 4 n-tiles (hi and lo)
            uint32_t bh[4][2], bl[4][2];
#pragma unroll
            for (int j = 0; j < 4; j++) {
                const int nrow = wn * 32 + j * 8 + r4;
                bh[j][0] = *(const uint32_t*)(Bsh + nrow * SPAD + kk + t2);
                bh[j][1] = *(const uint32_t*)(Bsh + nrow * SPAD + kk + t2 + 8);
                bl[j][0] = *(const uint32_t*)(Bsl + nrow * SPAD + kk + t2);
                bl[j][1] = *(const uint32_t*)(Bsl + nrow * SPAD + kk + t2 + 8);
            }
#pragma unroll
            for (int i = 0; i < 4; i++) {
                const int mrow = wm * 64 + i * 16 + r4;
                uint32_t ah[4], al[4];
                ah[0] = *(const uint32_t*)(Ash + mrow * SPAD + kk + t2);
                ah[1] = *(const uint32_t*)(Ash + (mrow + 8) * SPAD + kk + t2);
                ah[2] = *(const uint32_t*)(Ash + mrow * SPAD + kk + t2 + 8);
                ah[3] = *(const uint32_t*)(Ash + (mrow + 8) * SPAD + kk + t2 + 8);
                al[0] = *(const uint32_t*)(Asl + mrow * SPAD + kk + t2);
                al[1] = *(const uint32_t*)(Asl + (mrow + 8) * SPAD + kk + t2);
                al[2] = *(const uint32_t*)(Asl + mrow * SPAD + kk + t2 + 8);
                al[3] = *(const uint32_t*)(Asl + (mrow + 8) * SPAD + kk + t2 + 8);
#pragma unroll
                for (int j = 0; j < 4; j++) {
                    mma_bf16(acc[i][j], ah, bh[j]);
                    mma_bf16(acc[i][j], ah, bl[j]);
                    mma_bf16(acc[i][j], al, bh[j]);
                }
            }
        }
    }

    // ---------------- epilogue ----------------
    const float al_ = (OUT_MODE == 1) ? alpha[0] : 0.f;
#pragma unroll
    for (int i = 0; i < 4; i++) {
#pragma unroll
        for (int j = 0; j < 4; j++) {
            const int gm = m0 + wm * 64 + i * 16 + r4;
            const int gn = n0 + wn * 32 + j * 8 + t2;
            if (OUT_MODE == 0) {
                float2 v0 = make_float2(acc[i][j][0], acc[i][j][1]);
                float2 v1 = make_float2(acc[i][j][2], acc[i][j][3]);
                *(float2*)((float*)C0 + (size_t)gm * Nc + gn)       = v0;
                *(float2*)((float*)C0 + (size_t)(gm + 8) * Nc + gn) = v1;
            } else {
                const float bb0 = bias[gn], bb1 = bias[gn + 1];
#pragma unroll
                for (int h = 0; h < 2; h++) {
                    float v0 = acc[i][j][h * 2 + 0] + bb0;
                    float v1 = acc[i][j][h * 2 + 1] + bb1;
                    v0 = v0 >= 0.f ? v0 : al_ * v0;
                    v1 = v1 >= 0.f ? v1 : al_ * v1;
                    __nv_bfloat16 h0 = __float2bfloat16(v0), h1 = __float2bfloat16(v1);
                    __nv_bfloat162 hp; hp.x = h0; hp.y = h1;
                    __nv_bfloat162 lp;
                    lp.x = __float2bfloat16(v0 - __bfloat162float(h0));
                    lp.y = __float2bfloat16(v1 - __bfloat162float(h1));
                    const size_t go = ((size_t)(gm + h * 8) * Nc + gn) >> 1;
                    ((uint32_t*)C0)[go] = *(uint32_t*)&hp;
                    ((uint32_t*)C1)[go] = *(uint32_t*)&lp;
                }
            }
        }
    }
}

// out = prelu(out + b2)
__global__ void finalize_kernel(float4* __restrict__ out, const float* __restrict__ b2,
                                const float* __restrict__ alpha, long n4) {
    long i = (long)blockIdx.x * blockDim.x + threadIdx.x;
    if (i >= n4) return;
    float4 v = out[i];
    int d = (int)((i * 4) & (H2 - 1));
    float a = alpha[0];
    v.x += b2[d + 0]; v.y += b2[d + 1]; v.z += b2[d + 2]; v.w += b2[d + 3];
    v.x = v.x >= 0.f ? v.x : a * v.x;
    v.y = v.y >= 0.f ? v.y : a * v.y;
    v.z = v.z >= 0.f ? v.z : a * v.z;
    v.w = v.w >= 0.f ? v.w : a * v.w;
    out[i] = v;
}

// -------------------- launch --------------------
extern "C" void kernel_launch(void* const* d_in, const int* in_sizes, int n_in,
                              void* d_out, int out_size) {
    const float* x     = (const float*)d_in[0];
    const float* ew    = (const float*)d_in[1];
    const float* W1    = (const float*)d_in[2];
    const float* b1    = (const float*)d_in[3];
    const float* W2    = (const float*)d_in[4];
    const float* b2    = (const float*)d_in[5];
    const float* alpha = (const float*)d_in[6];
    const int*   eidx  = (const int*)  d_in[7];

    const int E = in_sizes[1];
    const int N = in_sizes[0] / IN_DIM;
    const int* row = eidx;
    const int* col = eidx + E;
    float* out = (float*)d_out;

    float *deg, *dinv, *agg1, *xw2;
    __nv_bfloat16 *a1hi, *a1lo, *f1hi, *f1lo, *w1thi, *w1tlo, *w2thi, *w2tlo;
    cudaGetSymbolAddress((void**)&deg,   g_deg);
    cudaGetSymbolAddress((void**)&dinv,  g_dinv);
    cudaGetSymbolAddress((void**)&agg1,  g_agg1);
    cudaGetSymbolAddress((void**)&xw2,   g_xw2);
    cudaGetSymbolAddress((void**)&a1hi,  g_a1hi);
    cudaGetSymbolAddress((void**)&a1lo,  g_a1lo);
    cudaGetSymbolAddress((void**)&f1hi,  g_f1hi);
    cudaGetSymbolAddress((void**)&f1lo,  g_f1lo);
    cudaGetSymbolAddress((void**)&w1thi, g_w1thi);
    cudaGetSymbolAddress((void**)&w1tlo, g_w1tlo);
    cudaGetSymbolAddress((void**)&w2thi, g_w2thi);
    cudaGetSymbolAddress((void**)&w2tlo, g_w2tlo);

    // 1) degrees + dinv; weight transposed splits (small, independent)
    deg_init<<<(N + 255) / 256, 256>>>(deg, N);
    deg_accum<<<(E + 255) / 256, 256>>>(col, ew, deg, E);
    deg_rsqrt<<<(N + 255) / 256, 256>>>(deg, dinv, N);
    decompT<<<(IN_DIM * H1 + 255) / 256, 256>>>(W1, w1thi, w1tlo, IN_DIM, H1);
    decompT<<<(H1 * H2 + 255) / 256, 256>>>(W2, w2thi, w2tlo, H1, H2);

    // 2) layer-1 aggregation at D=256: agg1 = A_norm @ x
    {
        long n4 = (long)N * (IN_DIM / 4);
        selfloop_init<<<(int)((n4 + 255) / 256), 256>>>((const float4*)x, (float4*)agg1, dinv, N, IN_DIM / 4);
        long threads = (long)E * 32;
        agg_edges<IN_DIM><<<(int)((threads + 255) / 256), 256>>>(
            (const float4*)x, (float4*)agg1, row, col, ew, dinv, E);
    }

    // 3) split agg1 -> bf16 hi/lo (padding rows stay zero from zero-init globals)
    {
        long n4 = (long)N * (IN_DIM / 4);
        decomp4<<<(int)((n4 + 255) / 256), 256>>>((const float4*)agg1, (uint2*)a1hi, (uint2*)a1lo, n4);
    }

    // 4) GEMM1 (HMMA): feat1(hi/lo) = prelu(agg1 @ W1 + b1)   [50048,256]x[256,512]
    {
        dim3 grid(H1 / 128, M_PAD / 128);
        gemm_mma<1><<<grid, 256>>>(a1hi, a1lo, w1thi, w1tlo, f1hi, f1lo, H1, IN_DIM, b1, alpha);
    }

    // 5) GEMM2 (HMMA): xw2(fp32) = feat1 @ W2   [50048,512]x[512,128]
    {
        dim3 grid(H2 / 128, M_PAD / 128);
        gemm_mma<0><<<grid, 256>>>(f1hi, f1lo, w2thi, w2tlo, xw2, nullptr, H2, H1, nullptr, nullptr);
    }

    // 6) layer-2 aggregation at D=128 into d_out
    {
        long n4 = (long)N * (H2 / 4);
        selfloop_init<<<(int)((n4 + 255) / 256), 256>>>((const float4*)xw2, (float4*)out, dinv, N, H2 / 4);
        long threads = (long)E * 32;
        agg_edges<H2><<<(int)((threads + 255) / 256), 256>>>(
            (const float4*)xw2, (float4*)out, row, col, ew, dinv, E);
    }

    // 7) out = prelu(out + b2)
    {
        long n4 = (long)N * (H2 / 4);
        finalize_kernel<<<(int)((n4 + 255) / 256), 256>>>((float4*)out, b2, alpha, n4);
    }
}

// round 8
// speedup vs baseline: 1.9749x; 1.2760x over previous
#include <cuda_runtime.h>
#include <cuda_bf16.h>
#include <cstdint>

#define N_NODES 50000
#define N_EDGES 800000
#define IN_DIM  256
#define H1      512
#define H2      128
#define M_PAD   50048   // multiple of 128

// -------------------- scratch --------------------
__device__ float g_deg [N_NODES];
__device__ float g_dinv[N_NODES];
__device__ int   g_counts[N_NODES];
__device__ int   g_cursor[N_NODES];
__device__ int   g_offs [N_NODES + 1];
__device__ int   g_srcid[N_EDGES];
__device__ float g_val  [N_EDGES];
__device__ float g_xw2 [(size_t)M_PAD * H2];               // feat1 @ W2 (fp32)
__device__ __nv_bfloat16 g_a1hi[(size_t)M_PAD * IN_DIM];   // agg1 split (gather1 out)
__device__ __nv_bfloat16 g_a1lo[(size_t)M_PAD * IN_DIM];
__device__ __nv_bfloat16 g_f1hi[(size_t)M_PAD * H1];       // feat1 split (GEMM1 out)
__device__ __nv_bfloat16 g_f1lo[(size_t)M_PAD * H1];
__device__ __nv_bfloat16 g_w1thi[(size_t)H1 * IN_DIM];     // W1^T split [512,256]
__device__ __nv_bfloat16 g_w1tlo[(size_t)H1 * IN_DIM];
__device__ __nv_bfloat16 g_w2thi[(size_t)H2 * H1];         // W2^T split [128,512]
__device__ __nv_bfloat16 g_w2tlo[(size_t)H2 * H1];

// -------------------- helpers --------------------
__device__ __forceinline__ void mma_bf16(float* c, const uint32_t* a, const uint32_t* b) {
    asm volatile(
        "mma.sync.aligned.m16n8k16.row.col.f32.bf16.bf16.f32 "
        "{%0,%1,%2,%3}, {%4,%5,%6,%7}, {%8,%9}, {%0,%1,%2,%3};"
        : "+f"(c[0]), "+f"(c[1]), "+f"(c[2]), "+f"(c[3])
        : "r"(a[0]), "r"(a[1]), "r"(a[2]), "r"(a[3]), "r"(b[0]), "r"(b[1]));
}

// split float4 into packed bf16 hi (uint2) and lo (uint2)
__device__ __forceinline__ void split4(float4 v, uint2& hi, uint2& lo) {
    __nv_bfloat16 h0 = __float2bfloat16(v.x), h1 = __float2bfloat16(v.y);
    __nv_bfloat16 h2 = __float2bfloat16(v.z), h3 = __float2bfloat16(v.w);
    __nv_bfloat162 hp0; hp0.x = h0; hp0.y = h1;
    __nv_bfloat162 hp1; hp1.x = h2; hp1.y = h3;
    __nv_bfloat162 lp0, lp1;
    lp0.x = __float2bfloat16(v.x - __bfloat162float(h0));
    lp0.y = __float2bfloat16(v.y - __bfloat162float(h1));
    lp1.x = __float2bfloat16(v.z - __bfloat162float(h2));
    lp1.y = __float2bfloat16(v.w - __bfloat162float(h3));
    hi = make_uint2(*(uint32_t*)&hp0, *(uint32_t*)&hp1);
    lo = make_uint2(*(uint32_t*)&lp0, *(uint32_t*)&lp1);
}

__device__ __forceinline__ float4 fma4(float4 a, float w, float4 v) {
    a.x = fmaf(w, v.x, a.x); a.y = fmaf(w, v.y, a.y);
    a.z = fmaf(w, v.z, a.z); a.w = fmaf(w, v.w, a.w);
    return a;
}

// -------------------- CSR build --------------------
__global__ void init_all(float* deg, int* counts, int* cursor, int n) {
    int i = blockIdx.x * blockDim.x + threadIdx.x;
    if (i < n) { deg[i] = 1.0f; counts[i] = 0; cursor[i] = 0; }
}

__global__ void edge_accum(const int* __restrict__ col, const float* __restrict__ ew,
                           float* deg, int* counts, int E) {
    int e = blockIdx.x * blockDim.x + threadIdx.x;
    if (e < E) {
        int c = col[e];
        atomicAdd(&deg[c], ew[e]);
        atomicAdd(&counts[c], 1);
    }
}

__global__ void deg_rsqrt(const float* __restrict__ deg, float* dinv, int n) {
    int i = blockIdx.x * blockDim.x + threadIdx.x;
    if (i < n) { float d = deg[i]; dinv[i] = d > 0.f ? rsqrtf(d) : 0.f; }
}

// single-block exclusive scan over n counts -> offs[0..n]
__global__ __launch_bounds__(1024)
void scan_offsets(const int* __restrict__ counts, int* __restrict__ offs, int n) {
    __shared__ int sh[1024];
    const int t = threadIdx.x;
    const int CH = (n + 1023) / 1024;
    const int base = t * CH;
    int sum = 0;
    for (int i = 0; i < CH; i++) { int j = base + i; if (j < n) sum += counts[j]; }
    sh[t] = sum;
    __syncthreads();
    for (int d = 1; d < 1024; d <<= 1) {
        int v = (t >= d) ? sh[t - d] : 0;
        __syncthreads();
        sh[t] += v;
        __syncthreads();
    }
    int run = (t == 0) ? 0 : sh[t - 1];
    for (int i = 0; i < CH; i++) {
        int j = base + i;
        if (j < n) { offs[j] = run; run += counts[j]; }
    }
    if (t == 1023) offs[n] = sh[1023];
}

__global__ void fill_csr(const int* __restrict__ row, const int* __restrict__ col,
                         const float* __restrict__ ew, const float* __restrict__ dinv,
                         const int* __restrict__ offs, int* cursor,
                         int* __restrict__ srcid, float* __restrict__ val, int E) {
    int e = blockIdx.x * blockDim.x + threadIdx.x;
    if (e >= E) return;
    int r = row[e], c = col[e];
    int pos = offs[c] + atomicAdd(&cursor[c], 1);
    srcid[pos] = r;
    val[pos] = dinv[r] * ew[e] * dinv[c];
}

// transpose + split: src[K,N] fp32 -> hi/lo[N,K] bf16
__global__ void decompT(const float* __restrict__ src, __nv_bfloat16* __restrict__ hi,
                        __nv_bfloat16* __restrict__ lo, int K, int N) {
    int i = blockIdx.x * blockDim.x + threadIdx.x;
    if (i >= K * N) return;
    int k = i / N, n = i % N;
    float v = src[i];
    __nv_bfloat16 h = __float2bfloat16(v);
    hi[(size_t)n * K + k] = h;
    lo[(size_t)n * K + k] = __float2bfloat16(v - __bfloat162float(h));
}

// -------------------- gather aggregations (warp per destination) ------------
// Layer 1: agg = selfloop + sum val*x[src]; emits bf16 hi/lo directly.
__global__ __launch_bounds__(256)
void gather1(const float4* __restrict__ x, const int* __restrict__ srcid,
             const float* __restrict__ val, const int* __restrict__ offs,
             const float* __restrict__ dinv,
             uint2* __restrict__ hi, uint2* __restrict__ lo, int n_nodes) {
    int node = blockIdx.x * 8 + (threadIdx.x >> 5);
    if (node >= n_nodes) return;
    const int lane = threadIdx.x & 31;
    const int s = offs[node], e = offs[node + 1];
    const float dv = dinv[node];
    const float sl = dv * dv;

    const float4* xr = x + (size_t)node * 64;
    float4 v0 = __ldg(xr + lane), v1 = __ldg(xr + lane + 32);
    float4 a0 = make_float4(sl * v0.x, sl * v0.y, sl * v0.z, sl * v0.w);
    float4 a1 = make_float4(sl * v1.x, sl * v1.y, sl * v1.z, sl * v1.w);

    int k = s;
    for (; k + 2 <= e; k += 2) {
        int   r0 = __ldg(srcid + k),  r1 = __ldg(srcid + k + 1);
        float w0 = __ldg(val + k),    w1 = __ldg(val + k + 1);
        const float4* s0 = x + (size_t)r0 * 64;
        const float4* s1 = x + (size_t)r1 * 64;
        float4 u0 = __ldg(s0 + lane), u1 = __ldg(s0 + lane + 32);
        float4 t0 = __ldg(s1 + lane), t1 = __ldg(s1 + lane + 32);
        a0 = fma4(a0, w0, u0); a1 = fma4(a1, w0, u1);
        a0 = fma4(a0, w1, t0); a1 = fma4(a1, w1, t1);
    }
    if (k < e) {
        int r0 = __ldg(srcid + k); float w0 = __ldg(val + k);
        const float4* s0 = x + (size_t)r0 * 64;
        a0 = fma4(a0, w0, __ldg(s0 + lane));
        a1 = fma4(a1, w0, __ldg(s0 + lane + 32));
    }

    uint2 h, l;
    split4(a0, h, l);
    hi[(size_t)node * 64 + lane] = h;
    lo[(size_t)node * 64 + lane] = l;
    split4(a1, h, l);
    hi[(size_t)node * 64 + 32 + lane] = h;
    lo[(size_t)node * 64 + 32 + lane] = l;
}

// Layer 2: out = prelu(selfloop + sum val*xw[src] + b2)
__global__ __launch_bounds__(256)
void gather2(const float4* __restrict__ xw, const int* __restrict__ srcid,
             const float* __restrict__ val, const int* __restrict__ offs,
             const float* __restrict__ dinv, const float* __restrict__ b2,
             const float* __restrict__ alpha, float4* __restrict__ out, int n_nodes) {
    int node = blockIdx.x * 8 + (threadIdx.x >> 5);
    if (node >= n_nodes) return;
    const int lane = threadIdx.x & 31;
    const int s = offs[node], e = offs[node + 1];
    const float dv = dinv[node];
    const float sl = dv * dv;

    float4 v = __ldg(xw + (size_t)node * 32 + lane);
    float4 a = make_float4(sl * v.x, sl * v.y, sl * v.z, sl * v.w);

    int k = s;
    for (; k + 2 <= e; k += 2) {
        int   r0 = __ldg(srcid + k),  r1 = __ldg(srcid + k + 1);
        float w0 = __ldg(val + k),    w1 = __ldg(val + k + 1);
        float4 u = __ldg(xw + (size_t)r0 * 32 + lane);
        float4 t = __ldg(xw + (size_t)r1 * 32 + lane);
        a = fma4(a, w0, u);
        a = fma4(a, w1, t);
    }
    if (k < e) {
        int r0 = __ldg(srcid + k); float w0 = __ldg(val + k);
        a = fma4(a, w0, __ldg(xw + (size_t)r0 * 32 + lane));
    }

    float4 bb = __ldg((const float4*)b2 + lane);
    float al = __ldg(alpha);
    a.x += bb.x; a.y += bb.y; a.z += bb.z; a.w += bb.w;
    a.x = a.x >= 0.f ? a.x : al * a.x;
    a.y = a.y >= 0.f ? a.y : al * a.y;
    a.z = a.z >= 0.f ? a.z : al * a.z;
    a.w = a.w >= 0.f ? a.w : al * a.w;
    out[(size_t)node * 32 + lane] = a;
}

// -------------------- bf16x3 GEMM via warp mma.sync (HMMA) --------------------
// C[M,Nc] = (Ahi+Alo)[M,K] @ (Bhi+Blo)^T, B stored [Nc,K] row-major.
// Block 128x128, 8 warps 2(m)x4(n), warp tile 64x32, BK=32.
// OUT_MODE 0: fp32 C0. OUT_MODE 1: bias+PReLU, emit bf16 hi(C0)/lo(C1).
#define SPAD 40

template <int OUT_MODE>
__global__ __launch_bounds__(256)
void gemm_mma(const __nv_bfloat16* __restrict__ Ahi, const __nv_bfloat16* __restrict__ Alo,
              const __nv_bfloat16* __restrict__ Bhi, const __nv_bfloat16* __restrict__ Blo,
              void* C0, void* C1, int Nc, int K,
              const float* __restrict__ bias, const float* __restrict__ alpha) {
    __shared__ __nv_bfloat16 Ash[128 * SPAD];
    __shared__ __nv_bfloat16 Asl[128 * SPAD];
    __shared__ __nv_bfloat16 Bsh[128 * SPAD];
    __shared__ __nv_bfloat16 Bsl[128 * SPAD];

    const int tid  = threadIdx.x;
    const int wid  = tid >> 5;
    const int lane = tid & 31;
    const int wm   = wid >> 2;
    const int wn   = wid & 3;
    const int m0   = blockIdx.y * 128;
    const int n0   = blockIdx.x * 128;
    const int r4   = lane >> 2;
    const int t2   = (lane & 3) * 2;

    float acc[4][4][4];
#pragma unroll
    for (int i = 0; i < 4; i++)
#pragma unroll
        for (int j = 0; j < 4; j++)
#pragma unroll
            for (int q = 0; q < 4; q++) acc[i][j][q] = 0.f;

    const int ldr = tid >> 2;
    const int ldq = tid & 3;

    for (int kc = 0; kc < K; kc += 32) {
        __syncthreads();
        {
            const __nv_bfloat16* gA_h = Ahi + (size_t)(m0 + ldr) * K + kc + ldq * 8;
            const __nv_bfloat16* gA_l = Alo + (size_t)(m0 + ldr) * K + kc + ldq * 8;
            const __nv_bfloat16* gB_h = Bhi + (size_t)(n0 + ldr) * K + kc + ldq * 8;
            const __nv_bfloat16* gB_l = Blo + (size_t)(n0 + ldr) * K + kc + ldq * 8;
#pragma unroll
            for (int h = 0; h < 2; h++) {
                const size_t go = (size_t)h * 64 * K;
                const int so = (ldr + h * 64) * SPAD + ldq * 8;
                *(uint4*)(Ash + so) = *(const uint4*)(gA_h + go);
                *(uint4*)(Asl + so) = *(const uint4*)(gA_l + go);
                *(uint4*)(Bsh + so) = *(const uint4*)(gB_h + go);
                *(uint4*)(Bsl + so) = *(const uint4*)(gB_l + go);
            }
        }
        __syncthreads();

#pragma unroll
        for (int kk = 0; kk < 32; kk += 16) {
            uint32_t bh[4][2], bl[4][2];
#pragma unroll
            for (int j = 0; j < 4; j++) {
                const int nrow = wn * 32 + j * 8 + r4;
                bh[j][0] = *(const uint32_t*)(Bsh + nrow * SPAD + kk + t2);
                bh[j][1] = *(const uint32_t*)(Bsh + nrow * SPAD + kk + t2 + 8);
                bl[j][0] = *(const uint32_t*)(Bsl + nrow * SPAD + kk + t2);
                bl[j][1] = *(const uint32_t*)(Bsl + nrow * SPAD + kk + t2 + 8);
            }
#pragma unroll
            for (int i = 0; i < 4; i++) {
                const int mrow = wm * 64 + i * 16 + r4;
                uint32_t ah[4], al[4];
                ah[0] = *(const uint32_t*)(Ash + mrow * SPAD + kk + t2);
                ah[1] = *(const uint32_t*)(Ash + (mrow + 8) * SPAD + kk + t2);
                ah[2] = *(const uint32_t*)(Ash + mrow * SPAD + kk + t2 + 8);
                ah[3] = *(const uint32_t*)(Ash + (mrow + 8) * SPAD + kk + t2 + 8);
                al[0] = *(const uint32_t*)(Asl + mrow * SPAD + kk + t2);
                al[1] = *(const uint32_t*)(Asl + (mrow + 8) * SPAD + kk + t2);
                al[2] = *(const uint32_t*)(Asl + mrow * SPAD + kk + t2 + 8);
                al[3] = *(const uint32_t*)(Asl + (mrow + 8) * SPAD + kk + t2 + 8);
#pragma unroll
                for (int j = 0; j < 4; j++) {
                    mma_bf16(acc[i][j], ah, bh[j]);
                    mma_bf16(acc[i][j], ah, bl[j]);
                    mma_bf16(acc[i][j], al, bh[j]);
                }
            }
        }
    }

    const float al_ = (OUT_MODE == 1) ? alpha[0] : 0.f;
#pragma unroll
    for (int i = 0; i < 4; i++) {
#pragma unroll
        for (int j = 0; j < 4; j++) {
            const int gm = m0 + wm * 64 + i * 16 + r4;
            const int gn = n0 + wn * 32 + j * 8 + t2;
            if (OUT_MODE == 0) {
                float2 v0 = make_float2(acc[i][j][0], acc[i][j][1]);
                float2 v1 = make_float2(acc[i][j][2], acc[i][j][3]);
                *(float2*)((float*)C0 + (size_t)gm * Nc + gn)       = v0;
                *(float2*)((float*)C0 + (size_t)(gm + 8) * Nc + gn) = v1;
            } else {
                const float bb0 = bias[gn], bb1 = bias[gn + 1];
#pragma unroll
                for (int h = 0; h < 2; h++) {
                    float v0 = acc[i][j][h * 2 + 0] + bb0;
                    float v1 = acc[i][j][h * 2 + 1] + bb1;
                    v0 = v0 >= 0.f ? v0 : al_ * v0;
                    v1 = v1 >= 0.f ? v1 : al_ * v1;
                    __nv_bfloat16 h0 = __float2bfloat16(v0), h1 = __float2bfloat16(v1);
                    __nv_bfloat162 hp; hp.x = h0; hp.y = h1;
                    __nv_bfloat162 lp;
                    lp.x = __float2bfloat16(v0 - __bfloat162float(h0));
                    lp.y = __float2bfloat16(v1 - __bfloat162float(h1));
                    const size_t go = ((size_t)(gm + h * 8) * Nc + gn) >> 1;
                    ((uint32_t*)C0)[go] = *(uint32_t*)&hp;
                    ((uint32_t*)C1)[go] = *(uint32_t*)&lp;
                }
            }
        }
    }
}

// -------------------- launch --------------------
extern "C" void kernel_launch(void* const* d_in, const int* in_sizes, int n_in,
                              void* d_out, int out_size) {
    const float* x     = (const float*)d_in[0];
    const float* ew    = (const float*)d_in[1];
    const float* W1    = (const float*)d_in[2];
    const float* b1    = (const float*)d_in[3];
    const float* W2    = (const float*)d_in[4];
    const float* b2    = (const float*)d_in[5];
    const float* alpha = (const float*)d_in[6];
    const int*   eidx  = (const int*)  d_in[7];

    const int E = in_sizes[1];
    const int N = in_sizes[0] / IN_DIM;
    const int* row = eidx;
    const int* col = eidx + E;
    float* out = (float*)d_out;

    float *deg, *dinv, *xw2, *val;
    int *counts, *cursor, *offs, *srcid;
    __nv_bfloat16 *a1hi, *a1lo, *f1hi, *f1lo, *w1thi, *w1tlo, *w2thi, *w2tlo;
    cudaGetSymbolAddress((void**)&deg,    g_deg);
    cudaGetSymbolAddress((void**)&dinv,   g_dinv);
    cudaGetSymbolAddress((void**)&counts, g_counts);
    cudaGetSymbolAddress((void**)&cursor, g_cursor);
    cudaGetSymbolAddress((void**)&offs,   g_offs);
    cudaGetSymbolAddress((void**)&srcid,  g_srcid);
    cudaGetSymbolAddress((void**)&val,    g_val);
    cudaGetSymbolAddress((void**)&xw2,    g_xw2);
    cudaGetSymbolAddress((void**)&a1hi,   g_a1hi);
    cudaGetSymbolAddress((void**)&a1lo,   g_a1lo);
    cudaGetSymbolAddress((void**)&f1hi,   g_f1hi);
    cudaGetSymbolAddress((void**)&f1lo,   g_f1lo);
    cudaGetSymbolAddress((void**)&w1thi,  g_w1thi);
    cudaGetSymbolAddress((void**)&w1tlo,  g_w1tlo);
    cudaGetSymbolAddress((void**)&w2thi,  g_w2thi);
    cudaGetSymbolAddress((void**)&w2tlo,  g_w2tlo);

    // 1) CSR build + degree normalization
    init_all<<<(N + 255) / 256, 256>>>(deg, counts, cursor, N);
    edge_accum<<<(E + 255) / 256, 256>>>(col, ew, deg, counts, E);
    deg_rsqrt<<<(N + 255) / 256, 256>>>(deg, dinv, N);
    scan_offsets<<<1, 1024>>>(counts, offs, N);
    fill_csr<<<(E + 255) / 256, 256>>>(row, col, ew, dinv, offs, cursor, srcid, val, E);

    // weight transposed splits (independent)
    decompT<<<(IN_DIM * H1 + 255) / 256, 256>>>(W1, w1thi, w1tlo, IN_DIM, H1);
    decompT<<<(H1 * H2 + 255) / 256, 256>>>(W2, w2thi, w2tlo, H1, H2);

    // 2) layer-1 aggregation (gather) -> bf16 hi/lo directly
    gather1<<<(N + 7) / 8, 256>>>((const float4*)x, srcid, val, offs, dinv,
                                  (uint2*)a1hi, (uint2*)a1lo, N);

    // 3) GEMM1 (HMMA): feat1(hi/lo) = prelu(agg1 @ W1 + b1)
    {
        dim3 grid(H1 / 128, M_PAD / 128);
        gemm_mma<1><<<grid, 256>>>(a1hi, a1lo, w1thi, w1tlo, f1hi, f1lo, H1, IN_DIM, b1, alpha);
    }

    // 4) GEMM2 (HMMA): xw2(fp32) = feat1 @ W2
    {
        dim3 grid(H2 / 128, M_PAD / 128);
        gemm_mma<0><<<grid, 256>>>(f1hi, f1lo, w2thi, w2tlo, xw2, nullptr, H2, H1, nullptr, nullptr);
    }

    // 5) layer-2 aggregation (gather) fused with bias + PReLU -> out
    gather2<<<(N + 7) / 8, 256>>>((const float4*)xw2, srcid, val, offs, dinv,
                                  b2, alpha, (float4*)out, N);
}

// round 9
// speedup vs baseline: 2.1187x; 1.0728x over previous
#include <cuda_runtime.h>
#include <cuda_bf16.h>
#include <cstdint>

#define N_NODES 50000
#define N_EDGES 800000
#define IN_DIM  256
#define H1      512
#define H2      128
#define M_PAD   50048   // multiple of 128

// -------------------- scratch --------------------
__device__ float g_deg [N_NODES];
__device__ float g_dinv[N_NODES];
__device__ int   g_counts[N_NODES];
__device__ int   g_cursor[N_NODES];
__device__ int   g_offs [N_NODES + 1];
__device__ int   g_bsum [256];
__device__ int   g_bases[256];
__device__ int   g_srcid[N_EDGES];
__device__ float g_val  [N_EDGES];
__device__ float g_xw2 [(size_t)M_PAD * H2];               // feat1 @ W2 (fp32)
__device__ __nv_bfloat16 g_a1hi[(size_t)M_PAD * IN_DIM];   // agg1 split (gather1 out)
__device__ __nv_bfloat16 g_a1lo[(size_t)M_PAD * IN_DIM];
__device__ __nv_bfloat16 g_f1hi[(size_t)M_PAD * H1];       // feat1 split (GEMM1 out)
__device__ __nv_bfloat16 g_f1lo[(size_t)M_PAD * H1];
__device__ __nv_bfloat16 g_w1thi[(size_t)H1 * IN_DIM];     // W1^T split [512,256]
__device__ __nv_bfloat16 g_w1tlo[(size_t)H1 * IN_DIM];
__device__ __nv_bfloat16 g_w2thi[(size_t)H2 * H1];         // W2^T split [128,512]
__device__ __nv_bfloat16 g_w2tlo[(size_t)H2 * H1];

// -------------------- helpers --------------------
__device__ __forceinline__ void mma_bf16(float* c, const uint32_t* a, const uint32_t* b) {
    asm volatile(
        "mma.sync.aligned.m16n8k16.row.col.f32.bf16.bf16.f32 "
        "{%0,%1,%2,%3}, {%4,%5,%6,%7}, {%8,%9}, {%0,%1,%2,%3};"
        : "+f"(c[0]), "+f"(c[1]), "+f"(c[2]), "+f"(c[3])
        : "r"(a[0]), "r"(a[1]), "r"(a[2]), "r"(a[3]), "r"(b[0]), "r"(b[1]));
}

__device__ __forceinline__ void split4(float4 v, uint2& hi, uint2& lo) {
    __nv_bfloat16 h0 = __float2bfloat16(v.x), h1 = __float2bfloat16(v.y);
    __nv_bfloat16 h2 = __float2bfloat16(v.z), h3 = __float2bfloat16(v.w);
    __nv_bfloat162 hp0; hp0.x = h0; hp0.y = h1;
    __nv_bfloat162 hp1; hp1.x = h2; hp1.y = h3;
    __nv_bfloat162 lp0, lp1;
    lp0.x = __float2bfloat16(v.x - __bfloat162float(h0));
    lp0.y = __float2bfloat16(v.y - __bfloat162float(h1));
    lp1.x = __float2bfloat16(v.z - __bfloat162float(h2));
    lp1.y = __float2bfloat16(v.w - __bfloat162float(h3));
    hi = make_uint2(*(uint32_t*)&hp0, *(uint32_t*)&hp1);
    lo = make_uint2(*(uint32_t*)&lp0, *(uint32_t*)&lp1);
}

__device__ __forceinline__ float4 fma4(float4 a, float w, float4 v) {
    a.x = fmaf(w, v.x, a.x); a.y = fmaf(w, v.y, a.y);
    a.z = fmaf(w, v.z, a.z); a.w = fmaf(w, v.w, a.w);
    return a;
}

// -------------------- CSR build --------------------
__global__ void init_all(float* deg, int* counts, int* cursor, int n) {
    int i = blockIdx.x * blockDim.x + threadIdx.x;
    if (i < n) { deg[i] = 1.0f; counts[i] = 0; cursor[i] = 0; }
}

__global__ void edge_accum(const int* __restrict__ col, const float* __restrict__ ew,
                           float* deg, int* counts, int E) {
    int e = blockIdx.x * blockDim.x + threadIdx.x;
    if (e < E) {
        int c = col[e];
        atomicAdd(&deg[c], ew[e]);
        atomicAdd(&counts[c], 1);
    }
}

__global__ void deg_rsqrt(const float* __restrict__ deg, float* dinv, int n) {
    int i = blockIdx.x * blockDim.x + threadIdx.x;
    if (i < n) { float d = deg[i]; dinv[i] = d > 0.f ? rsqrtf(d) : 0.f; }
}

// ---- 3-phase multi-block exclusive scan ----
__global__ void scan_part(const int* __restrict__ counts, int* __restrict__ offs,
                          int* __restrict__ bsum, int n) {
    __shared__ int sh[256];
    const int t = threadIdx.x;
    const int gid = blockIdx.x * 256 + t;
    int v = (gid < n) ? counts[gid] : 0;
    sh[t] = v;
    __syncthreads();
#pragma unroll
    for (int d = 1; d < 256; d <<= 1) {
        int u = (t >= d) ? sh[t - d] : 0;
        __syncthreads();
        sh[t] += u;
        __syncthreads();
    }
    if (gid < n) offs[gid] = sh[t] - v;   // exclusive within block
    if (t == 255) bsum[blockIdx.x] = sh[255];
}

__global__ void scan_bases(const int* __restrict__ bsum, int* __restrict__ bases,
                           int nb, int* __restrict__ offs, int n) {
    __shared__ int sh[256];
    const int t = threadIdx.x;
    int v = (t < nb) ? bsum[t] : 0;
    sh[t] = v;
    __syncthreads();
#pragma unroll
    for (int d = 1; d < 256; d <<= 1) {
        int u = (t >= d) ? sh[t - d] : 0;
        __syncthreads();
        sh[t] += u;
        __syncthreads();
    }
    if (t < nb) bases[t] = sh[t] - v;
    if (t == 255) offs[n] = sh[255];
}

__global__ void scan_add(int* __restrict__ offs, const int* __restrict__ bases, int n) {
    int gid = blockIdx.x * 256 + threadIdx.x;
    if (gid < n) offs[gid] += bases[blockIdx.x];
}

__global__ void fill_csr(const int* __restrict__ row, const int* __restrict__ col,
                         const float* __restrict__ ew, const float* __restrict__ dinv,
                         const int* __restrict__ offs, int* cursor,
                         int* __restrict__ srcid, float* __restrict__ val, int E) {
    int e = blockIdx.x * blockDim.x + threadIdx.x;
    if (e >= E) return;
    int r = row[e], c = col[e];
    int pos = offs[c] + atomicAdd(&cursor[c], 1);
    srcid[pos] = r;
    val[pos] = dinv[r] * ew[e] * dinv[c];
}

// transpose + split: src[K,N] fp32 -> hi/lo[N,K] bf16
__global__ void decompT(const float* __restrict__ src, __nv_bfloat16* __restrict__ hi,
                        __nv_bfloat16* __restrict__ lo, int K, int N) {
    int i = blockIdx.x * blockDim.x + threadIdx.x;
    if (i >= K * N) return;
    int k = i / N, n = i % N;
    float v = src[i];
    __nv_bfloat16 h = __float2bfloat16(v);
    hi[(size_t)n * K + k] = h;
    lo[(size_t)n * K + k] = __float2bfloat16(v - __bfloat162float(h));
}

// -------------------- gather aggregations (warp per destination) ------------
__global__ __launch_bounds__(256)
void gather1(const float4* __restrict__ x, const int* __restrict__ srcid,
             const float* __restrict__ val, const int* __restrict__ offs,
             const float* __restrict__ dinv,
             uint2* __restrict__ hi, uint2* __restrict__ lo, int n_nodes) {
    int node = blockIdx.x * 8 + (threadIdx.x >> 5);
    if (node >= n_nodes) return;
    const int lane = threadIdx.x & 31;
    const int s = offs[node], e = offs[node + 1];
    const float dv = dinv[node];
    const float sl = dv * dv;

    const float4* xr = x + (size_t)node * 64;
    float4 v0 = __ldg(xr + lane), v1 = __ldg(xr + lane + 32);
    float4 a0 = make_float4(sl * v0.x, sl * v0.y, sl * v0.z, sl * v0.w);
    float4 a1 = make_float4(sl * v1.x, sl * v1.y, sl * v1.z, sl * v1.w);

    int k = s;
    for (; k + 2 <= e; k += 2) {
        int   r0 = __ldg(srcid + k),  r1 = __ldg(srcid + k + 1);
        float w0 = __ldg(val + k),    w1 = __ldg(val + k + 1);
        const float4* s0 = x + (size_t)r0 * 64;
        const float4* s1 = x + (size_t)r1 * 64;
        float4 u0 = __ldg(s0 + lane), u1 = __ldg(s0 + lane + 32);
        float4 t0 = __ldg(s1 + lane), t1 = __ldg(s1 + lane + 32);
        a0 = fma4(a0, w0, u0); a1 = fma4(a1, w0, u1);
        a0 = fma4(a0, w1, t0); a1 = fma4(a1, w1, t1);
    }
    if (k < e) {
        int r0 = __ldg(srcid + k); float w0 = __ldg(val + k);
        const float4* s0 = x + (size_t)r0 * 64;
        a0 = fma4(a0, w0, __ldg(s0 + lane));
        a1 = fma4(a1, w0, __ldg(s0 + lane + 32));
    }

    uint2 h, l;
    split4(a0, h, l);
    hi[(size_t)node * 64 + lane] = h;
    lo[(size_t)node * 64 + lane] = l;
    split4(a1, h, l);
    hi[(size_t)node * 64 + 32 + lane] = h;
    lo[(size_t)node * 64 + 32 + lane] = l;
}

__global__ __launch_bounds__(256)
void gather2(const float4* __restrict__ xw, const int* __restrict__ srcid,
             const float* __restrict__ val, const int* __restrict__ offs,
             const float* __restrict__ dinv, const float* __restrict__ b2,
             const float* __restrict__ alpha, float4* __restrict__ out, int n_nodes) {
    int node = blockIdx.x * 8 + (threadIdx.x >> 5);
    if (node >= n_nodes) return;
    const int lane = threadIdx.x & 31;
    const int s = offs[node], e = offs[node + 1];
    const float dv = dinv[node];
    const float sl = dv * dv;

    float4 v = __ldg(xw + (size_t)node * 32 + lane);
    float4 a = make_float4(sl * v.x, sl * v.y, sl * v.z, sl * v.w);

    int k = s;
    for (; k + 2 <= e; k += 2) {
        int   r0 = __ldg(srcid + k),  r1 = __ldg(srcid + k + 1);
        float w0 = __ldg(val + k),    w1 = __ldg(val + k + 1);
        float4 u = __ldg(xw + (size_t)r0 * 32 + lane);
        float4 t = __ldg(xw + (size_t)r1 * 32 + lane);
        a = fma4(a, w0, u);
        a = fma4(a, w1, t);
    }
    if (k < e) {
        int r0 = __ldg(srcid + k); float w0 = __ldg(val + k);
        a = fma4(a, w0, __ldg(xw + (size_t)r0 * 32 + lane));
    }

    float4 bb = __ldg((const float4*)b2 + lane);
    float al = __ldg(alpha);
    a.x += bb.x; a.y += bb.y; a.z += bb.z; a.w += bb.w;
    a.x = a.x >= 0.f ? a.x : al * a.x;
    a.y = a.y >= 0.f ? a.y : al * a.y;
    a.z = a.z >= 0.f ? a.z : al * a.z;
    a.w = a.w >= 0.f ? a.w : al * a.w;
    out[(size_t)node * 32 + lane] = a;
}

// -------------------- bf16x3 GEMM via warp mma.sync (HMMA) --------------------
#define SPAD 40

template <int OUT_MODE>
__global__ __launch_bounds__(256)
void gemm_mma(const __nv_bfloat16* __restrict__ Ahi, const __nv_bfloat16* __restrict__ Alo,
              const __nv_bfloat16* __restrict__ Bhi, const __nv_bfloat16* __restrict__ Blo,
              void* C0, void* C1, int Nc, int K,
              const float* __restrict__ bias, const float* __restrict__ alpha) {
    __shared__ __nv_bfloat16 Ash[128 * SPAD];
    __shared__ __nv_bfloat16 Asl[128 * SPAD];
    __shared__ __nv_bfloat16 Bsh[128 * SPAD];
    __shared__ __nv_bfloat16 Bsl[128 * SPAD];

    const int tid  = threadIdx.x;
    const int wid  = tid >> 5;
    const int lane = tid & 31;
    const int wm   = wid >> 2;
    const int wn   = wid & 3;
    const int m0   = blockIdx.y * 128;
    const int n0   = blockIdx.x * 128;
    const int r4   = lane >> 2;
    const int t2   = (lane & 3) * 2;

    float acc[4][4][4];
#pragma unroll
    for (int i = 0; i < 4; i++)
#pragma unroll
        for (int j = 0; j < 4; j++)
#pragma unroll
            for (int q = 0; q < 4; q++) acc[i][j][q] = 0.f;

    const int ldr = tid >> 2;
    const int ldq = tid & 3;

    for (int kc = 0; kc < K; kc += 32) {
        __syncthreads();
        {
            const __nv_bfloat16* gA_h = Ahi + (size_t)(m0 + ldr) * K + kc + ldq * 8;
            const __nv_bfloat16* gA_l = Alo + (size_t)(m0 + ldr) * K + kc + ldq * 8;
            const __nv_bfloat16* gB_h = Bhi + (size_t)(n0 + ldr) * K + kc + ldq * 8;
            const __nv_bfloat16* gB_l = Blo + (size_t)(n0 + ldr) * K + kc + ldq * 8;
#pragma unroll
            for (int h = 0; h < 2; h++) {
                const size_t go = (size_t)h * 64 * K;
                const int so = (ldr + h * 64) * SPAD + ldq * 8;
                *(uint4*)(Ash + so) = *(const uint4*)(gA_h + go);
                *(uint4*)(Asl + so) = *(const uint4*)(gA_l + go);
                *(uint4*)(Bsh + so) = *(const uint4*)(gB_h + go);
                *(uint4*)(Bsl + so) = *(const uint4*)(gB_l + go);
            }
        }
        __syncthreads();

#pragma unroll
        for (int kk = 0; kk < 32; kk += 16) {
            uint32_t bh[4][2], bl[4][2];
#pragma unroll
            for (int j = 0; j < 4; j++) {
                const int nrow = wn * 32 + j * 8 + r4;
                bh[j][0] = *(const uint32_t*)(Bsh + nrow * SPAD + kk + t2);
                bh[j][1] = *(const uint32_t*)(Bsh + nrow * SPAD + kk + t2 + 8);
                bl[j][0] = *(const uint32_t*)(Bsl + nrow * SPAD + kk + t2);
                bl[j][1] = *(const uint32_t*)(Bsl + nrow * SPAD + kk + t2 + 8);
            }
#pragma unroll
            for (int i = 0; i < 4; i++) {
                const int mrow = wm * 64 + i * 16 + r4;
                uint32_t ah[4], al[4];
                ah[0] = *(const uint32_t*)(Ash + mrow * SPAD + kk + t2);
                ah[1] = *(const uint32_t*)(Ash + (mrow + 8) * SPAD + kk + t2);
                ah[2] = *(const uint32_t*)(Ash + mrow * SPAD + kk + t2 + 8);
                ah[3] = *(const uint32_t*)(Ash + (mrow + 8) * SPAD + kk + t2 + 8);
                al[0] = *(const uint32_t*)(Asl + mrow * SPAD + kk + t2);
                al[1] = *(const uint32_t*)(Asl + (mrow + 8) * SPAD + kk + t2);
                al[2] = *(const uint32_t*)(Asl + mrow * SPAD + kk + t2 + 8);
                al[3] = *(const uint32_t*)(Asl + (mrow + 8) * SPAD + kk + t2 + 8);
#pragma unroll
                for (int j = 0; j < 4; j++) {
                    mma_bf16(acc[i][j], ah, bh[j]);
                    mma_bf16(acc[i][j], ah, bl[j]);
                    mma_bf16(acc[i][j], al, bh[j]);
                }
            }
        }
    }

    const float al_ = (OUT_MODE == 1) ? alpha[0] : 0.f;
#pragma unroll
    for (int i = 0; i < 4; i++) {
#pragma unroll
        for (int j = 0; j < 4; j++) {
            const int gm = m0 + wm * 64 + i * 16 + r4;
            const int gn = n0 + wn * 32 + j * 8 + t2;
            if (OUT_MODE == 0) {
                float2 v0 = make_float2(acc[i][j][0], acc[i][j][1]);
                float2 v1 = make_float2(acc[i][j][2], acc[i][j][3]);
                *(float2*)((float*)C0 + (size_t)gm * Nc + gn)       = v0;
                *(float2*)((float*)C0 + (size_t)(gm + 8) * Nc + gn) = v1;
            } else {
                const float bb0 = bias[gn], bb1 = bias[gn + 1];
#pragma unroll
                for (int h = 0; h < 2; h++) {
                    float v0 = acc[i][j][h * 2 + 0] + bb0;
                    float v1 = acc[i][j][h * 2 + 1] + bb1;
                    v0 = v0 >= 0.f ? v0 : al_ * v0;
                    v1 = v1 >= 0.f ? v1 : al_ * v1;
                    __nv_bfloat16 h0 = __float2bfloat16(v0), h1 = __float2bfloat16(v1);
                    __nv_bfloat162 hp; hp.x = h0; hp.y = h1;
                    __nv_bfloat162 lp;
                    lp.x = __float2bfloat16(v0 - __bfloat162float(h0));
                    lp.y = __float2bfloat16(v1 - __bfloat162float(h1));
                    const size_t go = ((size_t)(gm + h * 8) * Nc + gn) >> 1;
                    ((uint32_t*)C0)[go] = *(uint32_t*)&hp;
                    ((uint32_t*)C1)[go] = *(uint32_t*)&lp;
                }
            }
        }
    }
}

// -------------------- launch --------------------
extern "C" void kernel_launch(void* const* d_in, const int* in_sizes, int n_in,
                              void* d_out, int out_size) {
    const float* x     = (const float*)d_in[0];
    const float* ew    = (const float*)d_in[1];
    const float* W1    = (const float*)d_in[2];
    const float* b1    = (const float*)d_in[3];
    const float* W2    = (const float*)d_in[4];
    const float* b2    = (const float*)d_in[5];
    const float* alpha = (const float*)d_in[6];
    const int*   eidx  = (const int*)  d_in[7];

    const int E = in_sizes[1];
    const int N = in_sizes[0] / IN_DIM;
    const int* row = eidx;
    const int* col = eidx + E;
    float* out = (float*)d_out;

    float *deg, *dinv, *xw2, *val;
    int *counts, *cursor, *offs, *srcid, *bsum, *bases;
    __nv_bfloat16 *a1hi, *a1lo, *f1hi, *f1lo, *w1thi, *w1tlo, *w2thi, *w2tlo;
    cudaGetSymbolAddress((void**)&deg,    g_deg);
    cudaGetSymbolAddress((void**)&dinv,   g_dinv);
    cudaGetSymbolAddress((void**)&counts, g_counts);
    cudaGetSymbolAddress((void**)&cursor, g_cursor);
    cudaGetSymbolAddress((void**)&offs,   g_offs);
    cudaGetSymbolAddress((void**)&bsum,   g_bsum);
    cudaGetSymbolAddress((void**)&bases,  g_bases);
    cudaGetSymbolAddress((void**)&srcid,  g_srcid);
    cudaGetSymbolAddress((void**)&val,    g_val);
    cudaGetSymbolAddress((void**)&xw2,    g_xw2);
    cudaGetSymbolAddress((void**)&a1hi,   g_a1hi);
    cudaGetSymbolAddress((void**)&a1lo,   g_a1lo);
    cudaGetSymbolAddress((void**)&f1hi,   g_f1hi);
    cudaGetSymbolAddress((void**)&f1lo,   g_f1lo);
    cudaGetSymbolAddress((void**)&w1thi,  g_w1thi);
    cudaGetSymbolAddress((void**)&w1tlo,  g_w1tlo);
    cudaGetSymbolAddress((void**)&w2thi,  g_w2thi);
    cudaGetSymbolAddress((void**)&w2tlo,  g_w2tlo);

    const int NB = (N + 255) / 256;   // 196 scan blocks (<= 256)

    // 1) CSR build + degree normalization
    init_all<<<NB, 256>>>(deg, counts, cursor, N);
    edge_accum<<<(E + 255) / 256, 256>>>(col, ew, deg, counts, E);
    deg_rsqrt<<<NB, 256>>>(deg, dinv, N);
    scan_part<<<NB, 256>>>(counts, offs, bsum, N);
    scan_bases<<<1, 256>>>(bsum, bases, NB, offs, N);
    scan_add<<<NB, 256>>>(offs, bases, N);
    fill_csr<<<(E + 255) / 256, 256>>>(row, col, ew, dinv, offs, cursor, srcid, val, E);

    // weight transposed splits (independent)
    decompT<<<(IN_DIM * H1 + 255) / 256, 256>>>(W1, w1thi, w1tlo, IN_DIM, H1);
    decompT<<<(H1 * H2 + 255) / 256, 256>>>(W2, w2thi, w2tlo, H1, H2);

    // 2) layer-1 aggregation (gather) -> bf16 hi/lo directly
    gather1<<<(N + 7) / 8, 256>>>((const float4*)x, srcid, val, offs, dinv,
                                  (uint2*)a1hi, (uint2*)a1lo, N);

    // 3) GEMM1 (HMMA): feat1(hi/lo) = prelu(agg1 @ W1 + b1)
    {
        dim3 grid(H1 / 128, M_PAD / 128);
        gemm_mma<1><<<grid, 256>>>(a1hi, a1lo, w1thi, w1tlo, f1hi, f1lo, H1, IN_DIM, b1, alpha);
    }

    // 4) GEMM2 (HMMA): xw2(fp32) = feat1 @ W2
    {
        dim3 grid(H2 / 128, M_PAD / 128);
        gemm_mma<0><<<grid, 256>>>(f1hi, f1lo, w2thi, w2tlo, xw2, nullptr, H2, H1, nullptr, nullptr);
    }

    // 5) layer-2 aggregation (gather) fused with bias + PReLU -> out
    gather2<<<(N + 7) / 8, 256>>>((const float4*)xw2, srcid, val, offs, dinv,
                                  b2, alpha, (float4*)out, N);
}

// round 10
// speedup vs baseline: 2.5998x; 1.2271x over previous
#include <cuda_runtime.h>
#include <cuda_bf16.h>
#include <cstdint>

#define N_NODES 50000
#define N_EDGES 800000
#define IN_DIM  256
#define H1      512
#define H2      128
#define M_PAD   50048   // multiple of 128

// -------------------- scratch --------------------
__device__ float g_deg [N_NODES];
__device__ float g_dinv[N_NODES];
__device__ int   g_counts[N_NODES];
__device__ int   g_cursor[N_NODES];
__device__ int   g_offs [N_NODES + 1];
__device__ int   g_bsum [256];
__device__ int   g_bases[256];
__device__ int   g_srcid[N_EDGES];
__device__ float g_val  [N_EDGES];
__device__ float g_xw2 [(size_t)M_PAD * H2];
__device__ __nv_bfloat16 g_a1hi[(size_t)M_PAD * IN_DIM];
__device__ __nv_bfloat16 g_a1lo[(size_t)M_PAD * IN_DIM];
__device__ __nv_bfloat16 g_f1hi[(size_t)M_PAD * H1];
__device__ __nv_bfloat16 g_f1lo[(size_t)M_PAD * H1];
__device__ __nv_bfloat16 g_w1thi[(size_t)H1 * IN_DIM];
__device__ __nv_bfloat16 g_w1tlo[(size_t)H1 * IN_DIM];
__device__ __nv_bfloat16 g_w2thi[(size_t)H2 * H1];
__device__ __nv_bfloat16 g_w2tlo[(size_t)H2 * H1];

// -------------------- helpers --------------------
__device__ __forceinline__ void mma_bf16(float* c, const uint32_t* a, const uint32_t* b) {
    asm volatile(
        "mma.sync.aligned.m16n8k16.row.col.f32.bf16.bf16.f32 "
        "{%0,%1,%2,%3}, {%4,%5,%6,%7}, {%8,%9}, {%0,%1,%2,%3};"
        : "+f"(c[0]), "+f"(c[1]), "+f"(c[2]), "+f"(c[3])
        : "r"(a[0]), "r"(a[1]), "r"(a[2]), "r"(a[3]), "r"(b[0]), "r"(b[1]));
}

__device__ __forceinline__ void ldsm4(uint32_t& r0, uint32_t& r1, uint32_t& r2,
                                      uint32_t& r3, uint32_t a) {
    asm volatile("ldmatrix.sync.aligned.m8n8.x4.shared.b16 {%0,%1,%2,%3}, [%4];"
                 : "=r"(r0), "=r"(r1), "=r"(r2), "=r"(r3) : "r"(a));
}

__device__ __forceinline__ void cp16(uint32_t saddr, const void* g) {
    asm volatile("cp.async.cg.shared.global [%0], [%1], 16;" :: "r"(saddr), "l"(g));
}
#define CP_COMMIT() asm volatile("cp.async.commit_group;" ::: "memory")
#define CP_WAIT(n)  asm volatile("cp.async.wait_group %0;" :: "n"(n) : "memory")

__device__ __forceinline__ uint32_t smem_u32(const void* p) {
    uint32_t a;
    asm("{ .reg .u64 t; cvta.to.shared.u64 t, %1; cvt.u32.u64 %0, t; }" : "=r"(a) : "l"(p));
    return a;
}

__device__ __forceinline__ void split4(float4 v, uint2& hi, uint2& lo) {
    __nv_bfloat16 h0 = __float2bfloat16(v.x), h1 = __float2bfloat16(v.y);
    __nv_bfloat16 h2 = __float2bfloat16(v.z), h3 = __float2bfloat16(v.w);
    __nv_bfloat162 hp0; hp0.x = h0; hp0.y = h1;
    __nv_bfloat162 hp1; hp1.x = h2; hp1.y = h3;
    __nv_bfloat162 lp0, lp1;
    lp0.x = __float2bfloat16(v.x - __bfloat162float(h0));
    lp0.y = __float2bfloat16(v.y - __bfloat162float(h1));
    lp1.x = __float2bfloat16(v.z - __bfloat162float(h2));
    lp1.y = __float2bfloat16(v.w - __bfloat162float(h3));
    hi = make_uint2(*(uint32_t*)&hp0, *(uint32_t*)&hp1);
    lo = make_uint2(*(uint32_t*)&lp0, *(uint32_t*)&lp1);
}

__device__ __forceinline__ float4 fma4(float4 a, float w, float4 v) {
    a.x = fmaf(w, v.x, a.x); a.y = fmaf(w, v.y, a.y);
    a.z = fmaf(w, v.z, a.z); a.w = fmaf(w, v.w, a.w);
    return a;
}

// -------------------- CSR build --------------------
__global__ void init_all(float* deg, int* counts, int* cursor, int n) {
    int i = blockIdx.x * blockDim.x + threadIdx.x;
    if (i < n) { deg[i] = 1.0f; counts[i] = 0; cursor[i] = 0; }
}

__global__ void edge_accum(const int* __restrict__ col, const float* __restrict__ ew,
                           float* deg, int* counts, int E) {
    int e = blockIdx.x * blockDim.x + threadIdx.x;
    if (e < E) {
        int c = col[e];
        atomicAdd(&deg[c], ew[e]);
        atomicAdd(&counts[c], 1);
    }
}

__global__ void deg_rsqrt(const float* __restrict__ deg, float* dinv, int n) {
    int i = blockIdx.x * blockDim.x + threadIdx.x;
    if (i < n) { float d = deg[i]; dinv[i] = d > 0.f ? rsqrtf(d) : 0.f; }
}

__global__ void scan_part(const int* __restrict__ counts, int* __restrict__ offs,
                          int* __restrict__ bsum, int n) {
    __shared__ int sh[256];
    const int t = threadIdx.x;
    const int gid = blockIdx.x * 256 + t;
    int v = (gid < n) ? counts[gid] : 0;
    sh[t] = v;
    __syncthreads();
#pragma unroll
    for (int d = 1; d < 256; d <<= 1) {
        int u = (t >= d) ? sh[t - d] : 0;
        __syncthreads();
        sh[t] += u;
        __syncthreads();
    }
    if (gid < n) offs[gid] = sh[t] - v;
    if (t == 255) bsum[blockIdx.x] = sh[255];
}

__global__ void scan_bases(const int* __restrict__ bsum, int* __restrict__ bases,
                           int nb, int* __restrict__ offs, int n) {
    __shared__ int sh[256];
    const int t = threadIdx.x;
    int v = (t < nb) ? bsum[t] : 0;
    sh[t] = v;
    __syncthreads();
#pragma unroll
    for (int d = 1; d < 256; d <<= 1) {
        int u = (t >= d) ? sh[t - d] : 0;
        __syncthreads();
        sh[t] += u;
        __syncthreads();
    }
    if (t < nb) bases[t] = sh[t] - v;
    if (t == 255) offs[n] = sh[255];
}

__global__ void scan_add(int* __restrict__ offs, const int* __restrict__ bases, int n) {
    int gid = blockIdx.x * 256 + threadIdx.x;
    if (gid < n) offs[gid] += bases[blockIdx.x];
}

__global__ void fill_csr(const int* __restrict__ row, const int* __restrict__ col,
                         const float* __restrict__ ew, const float* __restrict__ dinv,
                         const int* __restrict__ offs, int* cursor,
                         int* __restrict__ srcid, float* __restrict__ val, int E) {
    int e = blockIdx.x * blockDim.x + threadIdx.x;
    if (e >= E) return;
    int r = row[e], c = col[e];
    int pos = offs[c] + atomicAdd(&cursor[c], 1);
    srcid[pos] = r;
    val[pos] = dinv[r] * ew[e] * dinv[c];
}

__global__ void decompT(const float* __restrict__ src, __nv_bfloat16* __restrict__ hi,
                        __nv_bfloat16* __restrict__ lo, int K, int N) {
    int i = blockIdx.x * blockDim.x + threadIdx.x;
    if (i >= K * N) return;
    int k = i / N, n = i % N;
    float v = src[i];
    __nv_bfloat16 h = __float2bfloat16(v);
    hi[(size_t)n * K + k] = h;
    lo[(size_t)n * K + k] = __float2bfloat16(v - __bfloat162float(h));
}

// -------------------- gather aggregations (warp per destination) ------------
__global__ __launch_bounds__(256)
void gather1(const float4* __restrict__ x, const int* __restrict__ srcid,
             const float* __restrict__ val, const int* __restrict__ offs,
             const float* __restrict__ dinv,
             uint2* __restrict__ hi, uint2* __restrict__ lo, int n_nodes) {
    int node = blockIdx.x * 8 + (threadIdx.x >> 5);
    if (node >= n_nodes) return;
    const int lane = threadIdx.x & 31;
    const int s = offs[node], e = offs[node + 1];
    const float dv = dinv[node];
    const float sl = dv * dv;

    const float4* xr = x + (size_t)node * 64;
    float4 v0 = __ldg(xr + lane), v1 = __ldg(xr + lane + 32);
    float4 a0 = make_float4(sl * v0.x, sl * v0.y, sl * v0.z, sl * v0.w);
    float4 a1 = make_float4(sl * v1.x, sl * v1.y, sl * v1.z, sl * v1.w);

    int k = s;
    for (; k + 2 <= e; k += 2) {
        int   r0 = __ldg(srcid + k),  r1 = __ldg(srcid + k + 1);
        float w0 = __ldg(val + k),    w1 = __ldg(val + k + 1);
        const float4* s0 = x + (size_t)r0 * 64;
        const float4* s1 = x + (size_t)r1 * 64;
        float4 u0 = __ldg(s0 + lane), u1 = __ldg(s0 + lane + 32);
        float4 t0 = __ldg(s1 + lane), t1 = __ldg(s1 + lane + 32);
        a0 = fma4(a0, w0, u0); a1 = fma4(a1, w0, u1);
        a0 = fma4(a0, w1, t0); a1 = fma4(a1, w1, t1);
    }
    if (k < e) {
        int r0 = __ldg(srcid + k); float w0 = __ldg(val + k);
        const float4* s0 = x + (size_t)r0 * 64;
        a0 = fma4(a0, w0, __ldg(s0 + lane));
        a1 = fma4(a1, w0, __ldg(s0 + lane + 32));
    }

    uint2 h, l;
    split4(a0, h, l);
    hi[(size_t)node * 64 + lane] = h;
    lo[(size_t)node * 64 + lane] = l;
    split4(a1, h, l);
    hi[(size_t)node * 64 + 32 + lane] = h;
    lo[(size_t)node * 64 + 32 + lane] = l;
}

__global__ __launch_bounds__(256)
void gather2(const float4* __restrict__ xw, const int* __restrict__ srcid,
             const float* __restrict__ val, const int* __restrict__ offs,
             const float* __restrict__ dinv, const float* __restrict__ b2,
             const float* __restrict__ alpha, float4* __restrict__ out, int n_nodes) {
    int node = blockIdx.x * 8 + (threadIdx.x >> 5);
    if (node >= n_nodes) return;
    const int lane = threadIdx.x & 31;
    const int s = offs[node], e = offs[node + 1];
    const float dv = dinv[node];
    const float sl = dv * dv;

    float4 v = __ldg(xw + (size_t)node * 32 + lane);
    float4 a = make_float4(sl * v.x, sl * v.y, sl * v.z, sl * v.w);

    int k = s;
    for (; k + 2 <= e; k += 2) {
        int   r0 = __ldg(srcid + k),  r1 = __ldg(srcid + k + 1);
        float w0 = __ldg(val + k),    w1 = __ldg(val + k + 1);
        float4 u = __ldg(xw + (size_t)r0 * 32 + lane);
        float4 t = __ldg(xw + (size_t)r1 * 32 + lane);
        a = fma4(a, w0, u);
        a = fma4(a, w1, t);
    }
    if (k < e) {
        int r0 = __ldg(srcid + k); float w0 = __ldg(val + k);
        a = fma4(a, w0, __ldg(xw + (size_t)r0 * 32 + lane));
    }

    float4 bb = __ldg((const float4*)b2 + lane);
    float al = __ldg(alpha);
    a.x += bb.x; a.y += bb.y; a.z += bb.z; a.w += bb.w;
    a.x = a.x >= 0.f ? a.x : al * a.x;
    a.y = a.y >= 0.f ? a.y : al * a.y;
    a.z = a.z >= 0.f ? a.z : al * a.z;
    a.w = a.w >= 0.f ? a.w : al * a.w;
    out[(size_t)node * 32 + lane] = a;
}

// ---------- bf16x3 GEMM: HMMA + ldmatrix + cp.async double buffering ----------
// C[M,Nc] = (Ahi+Alo)[M,K] @ (Bhi+Blo)^T, B stored [Nc,K] row-major.
// Block 128x128, 8 warps 2(m)x4(n), warp tile 64x32, BK=32, 2-stage pipeline.
#define SPAD 40                         // smem row stride in bf16 (80B, 16B-aligned, LDSM conflict-free)
#define TILE_E (128 * SPAD)             // elements per tile
#define GEMM_SMEM_BYTES (2 * 4 * TILE_E * 2)   // 81920

template <int OUT_MODE>
__global__ __launch_bounds__(256)
void gemm_mma2(const __nv_bfloat16* __restrict__ Ahi, const __nv_bfloat16* __restrict__ Alo,
               const __nv_bfloat16* __restrict__ Bhi, const __nv_bfloat16* __restrict__ Blo,
               void* C0, void* C1, int Nc, int K,
               const float* __restrict__ bias, const float* __restrict__ alpha) {
    extern __shared__ __nv_bfloat16 sm[];
    const uint32_t sbase = smem_u32(sm);

    const int tid  = threadIdx.x;
    const int wid  = tid >> 5;
    const int lane = tid & 31;
    const int wm   = wid >> 2;          // 0..1
    const int wn   = wid & 3;           // 0..3
    const int m0   = blockIdx.y * 128;
    const int n0   = blockIdx.x * 128;
    const int r4   = lane >> 2;
    const int t2   = (lane & 3) * 2;

    float acc[4][4][4];
#pragma unroll
    for (int i = 0; i < 4; i++)
#pragma unroll
        for (int j = 0; j < 4; j++)
#pragma unroll
            for (int q = 0; q < 4; q++) acc[i][j][q] = 0.f;

    // gmem->smem mapping: thread loads 16B at (ldr, ldq*8) and (ldr+64, ldq*8) per tile
    const int ldr = tid >> 2;
    const int ldq = tid & 3;
    const __nv_bfloat16* gb[4] = {
        Ahi + (size_t)(m0 + ldr) * K + ldq * 8,
        Alo + (size_t)(m0 + ldr) * K + ldq * 8,
        Bhi + (size_t)(n0 + ldr) * K + ldq * 8,
        Blo + (size_t)(n0 + ldr) * K + ldq * 8 };

    auto tile_load = [&](int kc, int b) {
#pragma unroll
        for (int t = 0; t < 4; t++) {
#pragma unroll
            for (int h = 0; h < 2; h++) {
                uint32_t sa = sbase + (uint32_t)(((b * 4 + t) * TILE_E +
                                (ldr + h * 64) * SPAD + ldq * 8) * 2);
                cp16(sa, gb[t] + kc + (size_t)h * 64 * K);
            }
        }
    };

    // fragment addressing (lane-dependent, constant over loop)
    const int arow = wm * 64 + (lane & 15);
    const int aoff = (lane >> 4) * 8;
    const int brow = wn * 32 + (lane & 7) + ((lane >> 4) & 1) * 8;
    const int boff = ((lane >> 3) & 1) * 8;

    tile_load(0, 0);
    CP_COMMIT();

    int buf = 0;
    for (int kc = 0; kc < K; kc += 32) {
        const bool more = (kc + 32) < K;
        if (more) {
            tile_load(kc + 32, buf ^ 1);
            CP_COMMIT();
            CP_WAIT(1);
        } else {
            CP_WAIT(0);
        }
        __syncthreads();

        const uint32_t aH = sbase + (uint32_t)((buf * 4 + 0) * TILE_E * 2);
        const uint32_t aL = sbase + (uint32_t)((buf * 4 + 1) * TILE_E * 2);
        const uint32_t bH = sbase + (uint32_t)((buf * 4 + 2) * TILE_E * 2);
        const uint32_t bL = sbase + (uint32_t)((buf * 4 + 3) * TILE_E * 2);

#pragma unroll
        for (int kk = 0; kk < 32; kk += 16) {
            uint32_t bh[4][2], bl[4][2];
#pragma unroll
            for (int jp = 0; jp < 2; jp++) {
                uint32_t ad = bH + (uint32_t)(((brow + jp * 16) * SPAD + kk + boff) * 2);
                ldsm4(bh[2*jp][0], bh[2*jp][1], bh[2*jp+1][0], bh[2*jp+1][1], ad);
                ad = bL + (uint32_t)(((brow + jp * 16) * SPAD + kk + boff) * 2);
                ldsm4(bl[2*jp][0], bl[2*jp][1], bl[2*jp+1][0], bl[2*jp+1][1], ad);
            }
#pragma unroll
            for (int i = 0; i < 4; i++) {
                uint32_t ah[4], al[4];
                uint32_t ad = aH + (uint32_t)(((arow + i * 16) * SPAD + kk + aoff) * 2);
                ldsm4(ah[0], ah[1], ah[2], ah[3], ad);
                ad = aL + (uint32_t)(((arow + i * 16) * SPAD + kk + aoff) * 2);
                ldsm4(al[0], al[1], al[2], al[3], ad);
#pragma unroll
                for (int j = 0; j < 4; j++) {
                    mma_bf16(acc[i][j], ah, bh[j]);
                    mma_bf16(acc[i][j], ah, bl[j]);
                    mma_bf16(acc[i][j], al, bh[j]);
                }
            }
        }
        __syncthreads();
        buf ^= 1;
    }

    const float al_ = (OUT_MODE == 1) ? alpha[0] : 0.f;
#pragma unroll
    for (int i = 0; i < 4; i++) {
#pragma unroll
        for (int j = 0; j < 4; j++) {
            const int gm = m0 + wm * 64 + i * 16 + r4;
            const int gn = n0 + wn * 32 + j * 8 + t2;
            if (OUT_MODE == 0) {
                float2 v0 = make_float2(acc[i][j][0], acc[i][j][1]);
                float2 v1 = make_float2(acc[i][j][2], acc[i][j][3]);
                *(float2*)((float*)C0 + (size_t)gm * Nc + gn)       = v0;
                *(float2*)((float*)C0 + (size_t)(gm + 8) * Nc + gn) = v1;
            } else {
                const float bb0 = bias[gn], bb1 = bias[gn + 1];
#pragma unroll
                for (int h = 0; h < 2; h++) {
                    float v0 = acc[i][j][h * 2 + 0] + bb0;
                    float v1 = acc[i][j][h * 2 + 1] + bb1;
                    v0 = v0 >= 0.f ? v0 : al_ * v0;
                    v1 = v1 >= 0.f ? v1 : al_ * v1;
                    __nv_bfloat16 h0 = __float2bfloat16(v0), h1 = __float2bfloat16(v1);
                    __nv_bfloat162 hp; hp.x = h0; hp.y = h1;
                    __nv_bfloat162 lp;
                    lp.x = __float2bfloat16(v0 - __bfloat162float(h0));
                    lp.y = __float2bfloat16(v1 - __bfloat162float(h1));
                    const size_t go = ((size_t)(gm + h * 8) * Nc + gn) >> 1;
                    ((uint32_t*)C0)[go] = *(uint32_t*)&hp;
                    ((uint32_t*)C1)[go] = *(uint32_t*)&lp;
                }
            }
        }
    }
}

// -------------------- launch --------------------
extern "C" void kernel_launch(void* const* d_in, const int* in_sizes, int n_in,
                              void* d_out, int out_size) {
    const float* x     = (const float*)d_in[0];
    const float* ew    = (const float*)d_in[1];
    const float* W1    = (const float*)d_in[2];
    const float* b1    = (const float*)d_in[3];
    const float* W2    = (const float*)d_in[4];
    const float* b2    = (const float*)d_in[5];
    const float* alpha = (const float*)d_in[6];
    const int*   eidx  = (const int*)  d_in[7];

    const int E = in_sizes[1];
    const int N = in_sizes[0] / IN_DIM;
    const int* row = eidx;
    const int* col = eidx + E;
    float* out = (float*)d_out;

    float *deg, *dinv, *xw2, *val;
    int *counts, *cursor, *offs, *srcid, *bsum, *bases;
    __nv_bfloat16 *a1hi, *a1lo, *f1hi, *f1lo, *w1thi, *w1tlo, *w2thi, *w2tlo;
    cudaGetSymbolAddress((void**)&deg,    g_deg);
    cudaGetSymbolAddress((void**)&dinv,   g_dinv);
    cudaGetSymbolAddress((void**)&counts, g_counts);
    cudaGetSymbolAddress((void**)&cursor, g_cursor);
    cudaGetSymbolAddress((void**)&offs,   g_offs);
    cudaGetSymbolAddress((void**)&bsum,   g_bsum);
    cudaGetSymbolAddress((void**)&bases,  g_bases);
    cudaGetSymbolAddress((void**)&srcid,  g_srcid);
    cudaGetSymbolAddress((void**)&val,    g_val);
    cudaGetSymbolAddress((void**)&xw2,    g_xw2);
    cudaGetSymbolAddress((void**)&a1hi,   g_a1hi);
    cudaGetSymbolAddress((void**)&a1lo,   g_a1lo);
    cudaGetSymbolAddress((void**)&f1hi,   g_f1hi);
    cudaGetSymbolAddress((void**)&f1lo,   g_f1lo);
    cudaGetSymbolAddress((void**)&w1thi,  g_w1thi);
    cudaGetSymbolAddress((void**)&w1tlo,  g_w1tlo);
    cudaGetSymbolAddress((void**)&w2thi,  g_w2thi);
    cudaGetSymbolAddress((void**)&w2tlo,  g_w2tlo);

    static bool attr_set = false;
    if (!attr_set) {
        cudaFuncSetAttribute(gemm_mma2<0>, cudaFuncAttributeMaxDynamicSharedMemorySize, GEMM_SMEM_BYTES);
        cudaFuncSetAttribute(gemm_mma2<1>, cudaFuncAttributeMaxDynamicSharedMemorySize, GEMM_SMEM_BYTES);
        attr_set = true;
    }

    const int NB = (N + 255) / 256;

    // 1) CSR build + degree normalization
    init_all<<<NB, 256>>>(deg, counts, cursor, N);
    edge_accum<<<(E + 255) / 256, 256>>>(col, ew, deg, counts, E);
    deg_rsqrt<<<NB, 256>>>(deg, dinv, N);
    scan_part<<<NB, 256>>>(counts, offs, bsum, N);
    scan_bases<<<1, 256>>>(bsum, bases, NB, offs, N);
    scan_add<<<NB, 256>>>(offs, bases, N);
    fill_csr<<<(E + 255) / 256, 256>>>(row, col, ew, dinv, offs, cursor, srcid, val, E);

    // weight transposed splits
    decompT<<<(IN_DIM * H1 + 255) / 256, 256>>>(W1, w1thi, w1tlo, IN_DIM, H1);
    decompT<<<(H1 * H2 + 255) / 256, 256>>>(W2, w2thi, w2tlo, H1, H2);

    // 2) layer-1 aggregation (gather) -> bf16 hi/lo
    gather1<<<(N + 7) / 8, 256>>>((const float4*)x, srcid, val, offs, dinv,
                                  (uint2*)a1hi, (uint2*)a1lo, N);

    // 3) GEMM1: feat1(hi/lo) = prelu(agg1 @ W1 + b1)
    {
        dim3 grid(H1 / 128, M_PAD / 128);
        gemm_mma2<1><<<grid, 256, GEMM_SMEM_BYTES>>>(a1hi, a1lo, w1thi, w1tlo,
                                                     f1hi, f1lo, H1, IN_DIM, b1, alpha);
    }

    // 4) GEMM2: xw2(fp32) = feat1 @ W2
    {
        dim3 grid(H2 / 128, M_PAD / 128);
        gemm_mma2<0><<<grid, 256, GEMM_SMEM_BYTES>>>(f1hi, f1lo, w2thi, w2tlo,
                                                     xw2, nullptr, H2, H1, nullptr, nullptr);
    }

    // 5) layer-2 aggregation (gather) fused with bias + PReLU -> out
    gather2<<<(N + 7) / 8, 256>>>((const float4*)xw2, srcid, val, offs, dinv,
                                  b2, alpha, (float4*)out, N);
}

// round 11
// speedup vs baseline: 2.8255x; 1.0868x over previous
#include <cuda_runtime.h>
#include <cuda_bf16.h>
#include <cstdint>

#define N_NODES 50000
#define N_EDGES 800000
#define IN_DIM  256
#define H1      512
#define H2      128
#define M_PAD   50048   // multiple of 128

// -------------------- scratch --------------------
__device__ float g_deg [N_NODES];
__device__ float g_dinv[N_NODES];
__device__ int   g_counts[N_NODES];
__device__ int   g_cursor[N_NODES];
__device__ int   g_offs [N_NODES + 1];
__device__ int   g_bsum [256];
__device__ int   g_bases[256];
__device__ int   g_srcid[N_EDGES];
__device__ float g_val  [N_EDGES];
__device__ float g_xw2 [(size_t)M_PAD * H2];
__device__ __nv_bfloat16 g_a1hi[(size_t)M_PAD * IN_DIM];
__device__ __nv_bfloat16 g_a1lo[(size_t)M_PAD * IN_DIM];
__device__ __nv_bfloat16 g_f1hi[(size_t)M_PAD * H1];
__device__ __nv_bfloat16 g_f1lo[(size_t)M_PAD * H1];
__device__ __nv_bfloat16 g_w1thi[(size_t)H1 * IN_DIM];
__device__ __nv_bfloat16 g_w1tlo[(size_t)H1 * IN_DIM];
__device__ __nv_bfloat16 g_w2thi[(size_t)H2 * H1];
__device__ __nv_bfloat16 g_w2tlo[(size_t)H2 * H1];

// -------------------- helpers --------------------
__device__ __forceinline__ void mma_bf16(float* c, const uint32_t* a, const uint32_t* b) {
    asm volatile(
        "mma.sync.aligned.m16n8k16.row.col.f32.bf16.bf16.f32 "
        "{%0,%1,%2,%3}, {%4,%5,%6,%7}, {%8,%9}, {%0,%1,%2,%3};"
        : "+f"(c[0]), "+f"(c[1]), "+f"(c[2]), "+f"(c[3])
        : "r"(a[0]), "r"(a[1]), "r"(a[2]), "r"(a[3]), "r"(b[0]), "r"(b[1]));
}

__device__ __forceinline__ void ldsm4(uint32_t& r0, uint32_t& r1, uint32_t& r2,
                                      uint32_t& r3, uint32_t a) {
    asm volatile("ldmatrix.sync.aligned.m8n8.x4.shared.b16 {%0,%1,%2,%3}, [%4];"
                 : "=r"(r0), "=r"(r1), "=r"(r2), "=r"(r3) : "r"(a));
}

__device__ __forceinline__ void cp16(uint32_t saddr, const void* g) {
    asm volatile("cp.async.cg.shared.global [%0], [%1], 16;" :: "r"(saddr), "l"(g));
}
#define CP_COMMIT() asm volatile("cp.async.commit_group;" ::: "memory")
#define CP_WAIT(n)  asm volatile("cp.async.wait_group %0;" :: "n"(n) : "memory")

__device__ __forceinline__ uint32_t smem_u32(const void* p) {
    uint32_t a;
    asm("{ .reg .u64 t; cvta.to.shared.u64 t, %1; cvt.u32.u64 %0, t; }" : "=r"(a) : "l"(p));
    return a;
}

__device__ __forceinline__ void split4(float4 v, uint2& hi, uint2& lo) {
    __nv_bfloat16 h0 = __float2bfloat16(v.x), h1 = __float2bfloat16(v.y);
    __nv_bfloat16 h2 = __float2bfloat16(v.z), h3 = __float2bfloat16(v.w);
    __nv_bfloat162 hp0; hp0.x = h0; hp0.y = h1;
    __nv_bfloat162 hp1; hp1.x = h2; hp1.y = h3;
    __nv_bfloat162 lp0, lp1;
    lp0.x = __float2bfloat16(v.x - __bfloat162float(h0));
    lp0.y = __float2bfloat16(v.y - __bfloat162float(h1));
    lp1.x = __float2bfloat16(v.z - __bfloat162float(h2));
    lp1.y = __float2bfloat16(v.w - __bfloat162float(h3));
    hi = make_uint2(*(uint32_t*)&hp0, *(uint32_t*)&hp1);
    lo = make_uint2(*(uint32_t*)&lp0, *(uint32_t*)&lp1);
}

__device__ __forceinline__ float4 fma4(float4 a, float w, float4 v) {
    a.x = fmaf(w, v.x, a.x); a.y = fmaf(w, v.y, a.y);
    a.z = fmaf(w, v.z, a.z); a.w = fmaf(w, v.w, a.w);
    return a;
}

// -------------------- CSR build --------------------
__global__ void init_all(float* deg, int* counts, int* cursor, int n) {
    int i = blockIdx.x * blockDim.x + threadIdx.x;
    if (i < n) { deg[i] = 1.0f; counts[i] = 0; cursor[i] = 0; }
}

__global__ void edge_accum(const int* __restrict__ col, const float* __restrict__ ew,
                           float* deg, int* counts, int E) {
    int e = blockIdx.x * blockDim.x + threadIdx.x;
    if (e < E) {
        int c = col[e];
        atomicAdd(&deg[c], ew[e]);
        atomicAdd(&counts[c], 1);
    }
}

// fused: dinv = rsqrt(deg)  AND  block-local exclusive scan of counts
__global__ void rsqrt_scan(const float* __restrict__ deg, float* __restrict__ dinv,
                           const int* __restrict__ counts, int* __restrict__ offs,
                           int* __restrict__ bsum, int n) {
    __shared__ int sh[256];
    const int t = threadIdx.x;
    const int gid = blockIdx.x * 256 + t;
    if (gid < n) {
        float d = deg[gid];
        dinv[gid] = d > 0.f ? rsqrtf(d) : 0.f;
    }
    int v = (gid < n) ? counts[gid] : 0;
    sh[t] = v;
    __syncthreads();
#pragma unroll
    for (int d = 1; d < 256; d <<= 1) {
        int u = (t >= d) ? sh[t - d] : 0;
        __syncthreads();
        sh[t] += u;
        __syncthreads();
    }
    if (gid < n) offs[gid] = sh[t] - v;
    if (t == 255) bsum[blockIdx.x] = sh[255];
}

__global__ void scan_bases(const int* __restrict__ bsum, int* __restrict__ bases,
                           int nb, int* __restrict__ offs, int n) {
    __shared__ int sh[256];
    const int t = threadIdx.x;
    int v = (t < nb) ? bsum[t] : 0;
    sh[t] = v;
    __syncthreads();
#pragma unroll
    for (int d = 1; d < 256; d <<= 1) {
        int u = (t >= d) ? sh[t - d] : 0;
        __syncthreads();
        sh[t] += u;
        __syncthreads();
    }
    if (t < nb) bases[t] = sh[t] - v;
    if (t == 255) offs[n] = sh[255];
}

__global__ void scan_add(int* __restrict__ offs, const int* __restrict__ bases, int n) {
    int gid = blockIdx.x * 256 + threadIdx.x;
    if (gid < n) offs[gid] += bases[blockIdx.x];
}

__global__ void fill_csr(const int* __restrict__ row, const int* __restrict__ col,
                         const float* __restrict__ ew, const float* __restrict__ dinv,
                         const int* __restrict__ offs, int* cursor,
                         int* __restrict__ srcid, float* __restrict__ val, int E) {
    int e = blockIdx.x * blockDim.x + threadIdx.x;
    if (e >= E) return;
    int r = row[e], c = col[e];
    int pos = offs[c] + atomicAdd(&cursor[c], 1);
    srcid[pos] = r;
    val[pos] = dinv[r] * ew[e] * dinv[c];
}

// both weight transposes + splits in one launch
__global__ void decompW(const float* __restrict__ W1, const float* __restrict__ W2,
                        __nv_bfloat16* __restrict__ w1hi, __nv_bfloat16* __restrict__ w1lo,
                        __nv_bfloat16* __restrict__ w2hi, __nv_bfloat16* __restrict__ w2lo) {
    const int n1 = IN_DIM * H1;
    const int n2 = H1 * H2;
    int i = blockIdx.x * blockDim.x + threadIdx.x;
    if (i < n1) {
        int k = i / H1, n = i % H1;
        float v = W1[i];
        __nv_bfloat16 h = __float2bfloat16(v);
        w1hi[(size_t)n * IN_DIM + k] = h;
        w1lo[(size_t)n * IN_DIM + k] = __float2bfloat16(v - __bfloat162float(h));
    } else if (i < n1 + n2) {
        int j = i - n1;
        int k = j / H2, n = j % H2;
        float v = W2[j];
        __nv_bfloat16 h = __float2bfloat16(v);
        w2hi[(size_t)n * H1 + k] = h;
        w2lo[(size_t)n * H1 + k] = __float2bfloat16(v - __bfloat162float(h));
    }
}

// -------------------- gather aggregations (warp per destination, unroll-4) ---
__global__ __launch_bounds__(256)
void gather1(const float4* __restrict__ x, const int* __restrict__ srcid,
             const float* __restrict__ val, const int* __restrict__ offs,
             const float* __restrict__ dinv,
             uint2* __restrict__ hi, uint2* __restrict__ lo, int n_nodes) {
    int node = blockIdx.x * 8 + (threadIdx.x >> 5);
    if (node >= n_nodes) return;
    const int lane = threadIdx.x & 31;
    const int s = offs[node], e = offs[node + 1];
    const float dv = dinv[node];
    const float sl = dv * dv;

    const float4* xr = x + (size_t)node * 64;
    float4 v0 = __ldg(xr + lane), v1 = __ldg(xr + lane + 32);
    float4 a0 = make_float4(sl * v0.x, sl * v0.y, sl * v0.z, sl * v0.w);
    float4 a1 = make_float4(sl * v1.x, sl * v1.y, sl * v1.z, sl * v1.w);

    int k = s;
    for (; k + 4 <= e; k += 4) {
        int   r0 = __ldg(srcid + k),     r1 = __ldg(srcid + k + 1);
        int   r2 = __ldg(srcid + k + 2), r3 = __ldg(srcid + k + 3);
        float w0 = __ldg(val + k),       w1 = __ldg(val + k + 1);
        float w2 = __ldg(val + k + 2),   w3 = __ldg(val + k + 3);
        const float4* p0 = x + (size_t)r0 * 64;
        const float4* p1 = x + (size_t)r1 * 64;
        const float4* p2 = x + (size_t)r2 * 64;
        const float4* p3 = x + (size_t)r3 * 64;
        float4 u00 = __ldg(p0 + lane), u01 = __ldg(p0 + lane + 32);
        float4 u10 = __ldg(p1 + lane), u11 = __ldg(p1 + lane + 32);
        float4 u20 = __ldg(p2 + lane), u21 = __ldg(p2 + lane + 32);
        float4 u30 = __ldg(p3 + lane), u31 = __ldg(p3 + lane + 32);
        a0 = fma4(a0, w0, u00); a1 = fma4(a1, w0, u01);
        a0 = fma4(a0, w1, u10); a1 = fma4(a1, w1, u11);
        a0 = fma4(a0, w2, u20); a1 = fma4(a1, w2, u21);
        a0 = fma4(a0, w3, u30); a1 = fma4(a1, w3, u31);
    }
    for (; k < e; k++) {
        int r0 = __ldg(srcid + k); float w0 = __ldg(val + k);
        const float4* p0 = x + (size_t)r0 * 64;
        a0 = fma4(a0, w0, __ldg(p0 + lane));
        a1 = fma4(a1, w0, __ldg(p0 + lane + 32));
    }

    uint2 h, l;
    split4(a0, h, l);
    hi[(size_t)node * 64 + lane] = h;
    lo[(size_t)node * 64 + lane] = l;
    split4(a1, h, l);
    hi[(size_t)node * 64 + 32 + lane] = h;
    lo[(size_t)node * 64 + 32 + lane] = l;
}

__global__ __launch_bounds__(256)
void gather2(const float4* __restrict__ xw, const int* __restrict__ srcid,
             const float* __restrict__ val, const int* __restrict__ offs,
             const float* __restrict__ dinv, const float* __restrict__ b2,
             const float* __restrict__ alpha, float4* __restrict__ out, int n_nodes) {
    int node = blockIdx.x * 8 + (threadIdx.x >> 5);
    if (node >= n_nodes) return;
    const int lane = threadIdx.x & 31;
    const int s = offs[node], e = offs[node + 1];
    const float dv = dinv[node];
    const float sl = dv * dv;

    float4 v = __ldg(xw + (size_t)node * 32 + lane);
    float4 a = make_float4(sl * v.x, sl * v.y, sl * v.z, sl * v.w);

    int k = s;
    for (; k + 4 <= e; k += 4) {
        int   r0 = __ldg(srcid + k),     r1 = __ldg(srcid + k + 1);
        int   r2 = __ldg(srcid + k + 2), r3 = __ldg(srcid + k + 3);
        float w0 = __ldg(val + k),       w1 = __ldg(val + k + 1);
        float w2 = __ldg(val + k + 2),   w3 = __ldg(val + k + 3);
        float4 u0 = __ldg(xw + (size_t)r0 * 32 + lane);
        float4 u1 = __ldg(xw + (size_t)r1 * 32 + lane);
        float4 u2 = __ldg(xw + (size_t)r2 * 32 + lane);
        float4 u3 = __ldg(xw + (size_t)r3 * 32 + lane);
        a = fma4(a, w0, u0);
        a = fma4(a, w1, u1);
        a = fma4(a, w2, u2);
        a = fma4(a, w3, u3);
    }
    for (; k < e; k++) {
        int r0 = __ldg(srcid + k); float w0 = __ldg(val + k);
        a = fma4(a, w0, __ldg(xw + (size_t)r0 * 32 + lane));
    }

    float4 bb = __ldg((const float4*)b2 + lane);
    float al = __ldg(alpha);
    a.x += bb.x; a.y += bb.y; a.z += bb.z; a.w += bb.w;
    a.x = a.x >= 0.f ? a.x : al * a.x;
    a.y = a.y >= 0.f ? a.y : al * a.y;
    a.z = a.z >= 0.f ? a.z : al * a.z;
    a.w = a.w >= 0.f ? a.w : al * a.w;
    out[(size_t)node * 32 + lane] = a;
}

// ---------- bf16x3 GEMM: HMMA + ldmatrix + cp.async double buffering ----------
// C[M,Nc] = (Ahi+Alo)[M,K] @ (Bhi+Blo)^T, B stored [Nc,K] row-major.
// BM = 32*MI (MI=4 -> 128, MI=2 -> 64), BN=128, BK=32, 2-stage pipeline.
// 8 warps as 2(m) x 4(n); warp tile (MI*16) x 32.
#define SPAD 40   // smem row stride in bf16 (80B, 16B-aligned, LDSM conflict-free)

template <int OUT_MODE, int MI>
__global__ __launch_bounds__(256)
void gemm_mma2(const __nv_bfloat16* __restrict__ Ahi, const __nv_bfloat16* __restrict__ Alo,
               const __nv_bfloat16* __restrict__ Bhi, const __nv_bfloat16* __restrict__ Blo,
               void* C0, void* C1, int Nc, int K,
               const float* __restrict__ bias, const float* __restrict__ alpha) {
    constexpr int BM = 32 * MI;
    constexpr int A_TILE = BM * SPAD;      // elements
    constexpr int B_TILE = 128 * SPAD;
    constexpr int STAGE  = 2 * A_TILE + 2 * B_TILE;

    extern __shared__ __nv_bfloat16 sm[];
    const uint32_t sbase = smem_u32(sm);

    const int tid  = threadIdx.x;
    const int wid  = tid >> 5;
    const int lane = tid & 31;
    const int wm   = wid >> 2;          // 0..1
    const int wn   = wid & 3;           // 0..3
    const int m0   = blockIdx.y * BM;
    const int n0   = blockIdx.x * 128;
    const int r4   = lane >> 2;
    const int t2   = (lane & 3) * 2;

    float acc[MI][4][4];
#pragma unroll
    for (int i = 0; i < MI; i++)
#pragma unroll
        for (int j = 0; j < 4; j++)
#pragma unroll
            for (int q = 0; q < 4; q++) acc[i][j][q] = 0.f;

    const int ldr = tid >> 2;           // 0..63
    const int ldq = tid & 3;
    const __nv_bfloat16* gAh = Ahi + (size_t)(m0 + ldr) * K + ldq * 8;
    const __nv_bfloat16* gAl = Alo + (size_t)(m0 + ldr) * K + ldq * 8;
    const __nv_bfloat16* gBh = Bhi + (size_t)(n0 + ldr) * K + ldq * 8;
    const __nv_bfloat16* gBl = Blo + (size_t)(n0 + ldr) * K + ldq * 8;

    auto tile_load = [&](int kc, int b) {
#pragma unroll
        for (int h = 0; h < MI / 2; h++) {   // A: BM rows
            uint32_t sa = sbase + (uint32_t)((b * STAGE + (ldr + h * 64) * SPAD + ldq * 8) * 2);
            cp16(sa, gAh + kc + (size_t)h * 64 * K);
            sa = sbase + (uint32_t)((b * STAGE + A_TILE + (ldr + h * 64) * SPAD + ldq * 8) * 2);
            cp16(sa, gAl + kc + (size_t)h * 64 * K);
        }
#pragma unroll
        for (int h = 0; h < 2; h++) {        // B: 128 rows
            uint32_t sa = sbase + (uint32_t)((b * STAGE + 2 * A_TILE +
                              (ldr + h * 64) * SPAD + ldq * 8) * 2);
            cp16(sa, gBh + kc + (size_t)h * 64 * K);
            sa = sbase + (uint32_t)((b * STAGE + 2 * A_TILE + B_TILE +
                              (ldr + h * 64) * SPAD + ldq * 8) * 2);
            cp16(sa, gBl + kc + (size_t)h * 64 * K);
        }
    };

    const int arow = wm * (MI * 16) + (lane & 15);
    const int aoff = (lane >> 4) * 8;
    const int brow = wn * 32 + (lane & 7) + ((lane >> 4) & 1) * 8;
    const int boff = ((lane >> 3) & 1) * 8;

    tile_load(0, 0);
    CP_COMMIT();

    int buf = 0;
    for (int kc = 0; kc < K; kc += 32) {
        const bool more = (kc + 32) < K;
        if (more) {
            tile_load(kc + 32, buf ^ 1);
            CP_COMMIT();
            CP_WAIT(1);
        } else {
            CP_WAIT(0);
        }
        __syncthreads();

        const uint32_t aH = sbase + (uint32_t)((buf * STAGE) * 2);
        const uint32_t aL = aH + (uint32_t)(A_TILE * 2);
        const uint32_t bH = aH + (uint32_t)(2 * A_TILE * 2);
        const uint32_t bL = bH + (uint32_t)(B_TILE * 2);

#pragma unroll
        for (int kk = 0; kk < 32; kk += 16) {
            uint32_t bh[4][2], bl[4][2];
#pragma unroll
            for (int jp = 0; jp < 2; jp++) {
                uint32_t ad = bH + (uint32_t)(((brow + jp * 16) * SPAD + kk + boff) * 2);
                ldsm4(bh[2*jp][0], bh[2*jp][1], bh[2*jp+1][0], bh[2*jp+1][1], ad);
                ad = bL + (uint32_t)(((brow + jp * 16) * SPAD + kk + boff) * 2);
                ldsm4(bl[2*jp][0], bl[2*jp][1], bl[2*jp+1][0], bl[2*jp+1][1], ad);
            }
#pragma unroll
            for (int i = 0; i < MI; i++) {
                uint32_t ah[4], al[4];
                uint32_t ad = aH + (uint32_t)(((arow + i * 16) * SPAD + kk + aoff) * 2);
                ldsm4(ah[0], ah[1], ah[2], ah[3], ad);
                ad = aL + (uint32_t)(((arow + i * 16) * SPAD + kk + aoff) * 2);
                ldsm4(al[0], al[1], al[2], al[3], ad);
#pragma unroll
                for (int j = 0; j < 4; j++) {
                    mma_bf16(acc[i][j], ah, bh[j]);
                    mma_bf16(acc[i][j], ah, bl[j]);
                    mma_bf16(acc[i][j], al, bh[j]);
                }
            }
        }
        __syncthreads();
        buf ^= 1;
    }

    const float al_ = (OUT_MODE == 1) ? alpha[0] : 0.f;
#pragma unroll
    for (int i = 0; i < MI; i++) {
#pragma unroll
        for (int j = 0; j < 4; j++) {
            const int gm = m0 + wm * (MI * 16) + i * 16 + r4;
            const int gn = n0 + wn * 32 + j * 8 + t2;
            if (OUT_MODE == 0) {
                float2 v0 = make_float2(acc[i][j][0], acc[i][j][1]);
                float2 v1 = make_float2(acc[i][j][2], acc[i][j][3]);
                *(float2*)((float*)C0 + (size_t)gm * Nc + gn)       = v0;
                *(float2*)((float*)C0 + (size_t)(gm + 8) * Nc + gn) = v1;
            } else {
                const float bb0 = bias[gn], bb1 = bias[gn + 1];
#pragma unroll
                for (int h = 0; h < 2; h++) {
                    float v0 = acc[i][j][h * 2 + 0] + bb0;
                    float v1 = acc[i][j][h * 2 + 1] + bb1;
                    v0 = v0 >= 0.f ? v0 : al_ * v0;
                    v1 = v1 >= 0.f ? v1 : al_ * v1;
                    __nv_bfloat16 h0 = __float2bfloat16(v0), h1 = __float2bfloat16(v1);
                    __nv_bfloat162 hp; hp.x = h0; hp.y = h1;
                    __nv_bfloat162 lp;
                    lp.x = __float2bfloat16(v0 - __bfloat162float(h0));
                    lp.y = __float2bfloat16(v1 - __bfloat162float(h1));
                    const size_t go = ((size_t)(gm + h * 8) * Nc + gn) >> 1;
                    ((uint32_t*)C0)[go] = *(uint32_t*)&hp;
                    ((uint32_t*)C1)[go] = *(uint32_t*)&lp;
                }
            }
        }
    }
}

#define SMEM_MI4 ((2 * (2 * 128 * SPAD + 2 * 128 * SPAD)) * 2)   // 81920 B
#define SMEM_MI2 ((2 * (2 * 64 * SPAD + 2 * 128 * SPAD)) * 2)    // 61440 B

// -------------------- launch --------------------
extern "C" void kernel_launch(void* const* d_in, const int* in_sizes, int n_in,
                              void* d_out, int out_size) {
    const float* x     = (const float*)d_in[0];
    const float* ew    = (const float*)d_in[1];
    const float* W1    = (const float*)d_in[2];
    const float* b1    = (const float*)d_in[3];
    const float* W2    = (const float*)d_in[4];
    const float* b2    = (const float*)d_in[5];
    const float* alpha = (const float*)d_in[6];
    const int*   eidx  = (const int*)  d_in[7];

    const int E = in_sizes[1];
    const int N = in_sizes[0] / IN_DIM;
    const int* row = eidx;
    const int* col = eidx + E;
    float* out = (float*)d_out;

    float *deg, *dinv, *xw2, *val;
    int *counts, *cursor, *offs, *srcid, *bsum, *bases;
    __nv_bfloat16 *a1hi, *a1lo, *f1hi, *f1lo, *w1thi, *w1tlo, *w2thi, *w2tlo;
    cudaGetSymbolAddress((void**)&deg,    g_deg);
    cudaGetSymbolAddress((void**)&dinv,   g_dinv);
    cudaGetSymbolAddress((void**)&counts, g_counts);
    cudaGetSymbolAddress((void**)&cursor, g_cursor);
    cudaGetSymbolAddress((void**)&offs,   g_offs);
    cudaGetSymbolAddress((void**)&bsum,   g_bsum);
    cudaGetSymbolAddress((void**)&bases,  g_bases);
    cudaGetSymbolAddress((void**)&srcid,  g_srcid);
    cudaGetSymbolAddress((void**)&val,    g_val);
    cudaGetSymbolAddress((void**)&xw2,    g_xw2);
    cudaGetSymbolAddress((void**)&a1hi,   g_a1hi);
    cudaGetSymbolAddress((void**)&a1lo,   g_a1lo);
    cudaGetSymbolAddress((void**)&f1hi,   g_f1hi);
    cudaGetSymbolAddress((void**)&f1lo,   g_f1lo);
    cudaGetSymbolAddress((void**)&w1thi,  g_w1thi);
    cudaGetSymbolAddress((void**)&w1tlo,  g_w1tlo);
    cudaGetSymbolAddress((void**)&w2thi,  g_w2thi);
    cudaGetSymbolAddress((void**)&w2tlo,  g_w2tlo);

    static bool attr_set = false;
    if (!attr_set) {
        cudaFuncSetAttribute((const void*)gemm_mma2<1, 4>, cudaFuncAttributeMaxDynamicSharedMemorySize, SMEM_MI4);
        cudaFuncSetAttribute((const void*)gemm_mma2<0, 2>, cudaFuncAttributeMaxDynamicSharedMemorySize, SMEM_MI2);
        attr_set = true;
    }

    const int NB = (N + 255) / 256;

    // 1) CSR build + degree normalization
    init_all<<<NB, 256>>>(deg, counts, cursor, N);
    edge_accum<<<(E + 255) / 256, 256>>>(col, ew, deg, counts, E);
    rsqrt_scan<<<NB, 256>>>(deg, dinv, counts, offs, bsum, N);
    scan_bases<<<1, 256>>>(bsum, bases, NB, offs, N);
    scan_add<<<NB, 256>>>(offs, bases, N);
    fill_csr<<<(E + 255) / 256, 256>>>(row, col, ew, dinv, offs, cursor, srcid, val, E);

    // weight transposed splits (one launch)
    decompW<<<(IN_DIM * H1 + H1 * H2 + 255) / 256, 256>>>(W1, W2, w1thi, w1tlo, w2thi, w2tlo);

    // 2) layer-1 aggregation (gather, unroll-4) -> bf16 hi/lo
    gather1<<<(N + 7) / 8, 256>>>((const float4*)x, srcid, val, offs, dinv,
                                  (uint2*)a1hi, (uint2*)a1lo, N);

    // 3) GEMM1: feat1(hi/lo) = prelu(agg1 @ W1 + b1)   BM=128
    {
        dim3 grid(H1 / 128, M_PAD / 128);
        gemm_mma2<1, 4><<<grid, 256, SMEM_MI4>>>(a1hi, a1lo, w1thi, w1tlo,
                                                 f1hi, f1lo, H1, IN_DIM, b1, alpha);
    }

    // 4) GEMM2: xw2(fp32) = feat1 @ W2   BM=64 for wave balance
    {
        dim3 grid(H2 / 128, M_PAD / 64);
        gemm_mma2<0, 2><<<grid, 256, SMEM_MI2>>>(f1hi, f1lo, w2thi, w2tlo,
                                                 xw2, nullptr, H2, H1, nullptr, nullptr);
    }

    // 5) layer-2 aggregation (gather, unroll-4) fused with bias + PReLU -> out
    gather2<<<(N + 7) / 8, 256>>>((const float4*)xw2, srcid, val, offs, dinv,
                                  b2, alpha, (float4*)out, N);
}